// round 2
// baseline (speedup 1.0000x reference)
#include <cuda_runtime.h>
#include <math.h>

#define T_TOT 65536
#define C_DIM 256
#define M_DIM 128
#define SHRINKV 0.0025f
#define EPSV 1e-12f

// ---------------- scratch (static device allocations) ----------------
__device__ float g_S[(size_t)M_DIM * T_TOT];   // 33.5 MB: exp(scores) -> then shrunk h
__device__ float g_rowsum[M_DIM];
__device__ float g_l1[M_DIM];
__device__ float g_addmem[M_DIM * C_DIM];      // raw (pre-l1-normalize) accumulation
__device__ float g_newmem[M_DIM * C_DIM];

// ---------------- K0: zero accumulators (graph-replay safe) ----------------
__global__ void k0_init() {
    int i = blockIdx.x * blockDim.x + threadIdx.x;
    if (i < M_DIM) { g_rowsum[i] = 0.f; g_l1[i] = 0.f; }
    if (i < M_DIM * C_DIM) g_addmem[i] = 0.f;
}

// ---------------- K1: S[m][t] = exp(mem[m] . q[t]); rowsum[m] += ... ----------------
// block: 128 t x 128 m tile, 256 threads, 8x8 micro-tile (interleaved by 16)
__global__ __launch_bounds__(256) void k1_scores(const float* __restrict__ q,
                                                 const float* __restrict__ mem) {
    __shared__ float As[16][132];   // As[k][m] = mem[m][k0+k]
    __shared__ float Bs[16][132];   // Bs[k][t] = q[t0+t][k0+k]
    __shared__ float rsum[128];

    int tid = threadIdx.x;
    int tx = tid & 15, ty = tid >> 4;
    int t0 = blockIdx.x * 128;

    float acc[8][8];
#pragma unroll
    for (int i = 0; i < 8; i++)
#pragma unroll
        for (int j = 0; j < 8; j++) acc[i][j] = 0.f;

    int lm = tid >> 1;            // 0..127
    int kb = (tid & 1) * 8;       // 0 or 8

    for (int k0 = 0; k0 < C_DIM; k0 += 16) {
#pragma unroll
        for (int u = 0; u < 8; u++)
            As[kb + u][lm] = mem[lm * C_DIM + k0 + kb + u];
#pragma unroll
        for (int u = 0; u < 8; u++)
            Bs[kb + u][lm] = q[(size_t)(t0 + lm) * C_DIM + k0 + kb + u];
        __syncthreads();
#pragma unroll
        for (int k = 0; k < 16; k++) {
            float a[8], b[8];
#pragma unroll
            for (int i = 0; i < 8; i++) a[i] = As[k][ty + i * 16];
#pragma unroll
            for (int j = 0; j < 8; j++) b[j] = Bs[k][tx + j * 16];
#pragma unroll
            for (int i = 0; i < 8; i++)
#pragma unroll
                for (int j = 0; j < 8; j++) acc[i][j] += a[i] * b[j];
        }
        __syncthreads();
    }

    if (tid < 128) rsum[tid] = 0.f;
    __syncthreads();

#pragma unroll
    for (int i = 0; i < 8; i++) {
        float part = 0.f;
        int m = ty + i * 16;
#pragma unroll
        for (int j = 0; j < 8; j++) {
            float e = __expf(acc[i][j]);
            acc[i][j] = e;
            part += e;
            g_S[(size_t)m * T_TOT + t0 + tx + j * 16] = e;
        }
        atomicAdd(&rsum[m], part);
    }
    __syncthreads();
    if (tid < 128) atomicAdd(&g_rowsum[tid], rsum[tid]);
}

// ---------------- K2: a = S/rowsum; h = hardshrink_relu(a); l1[m] += sum(h) ------------
__global__ __launch_bounds__(256) void k2_shrink() {
    int m = blockIdx.y;
    int base = blockIdx.x * 2048 + threadIdx.x;
    float inv = 1.0f / g_rowsum[m];
    float lsum = 0.f;
#pragma unroll
    for (int u = 0; u < 8; u++) {
        size_t idx = (size_t)m * T_TOT + base + u * 256;
        float a = g_S[idx] * inv;
        float d = a - SHRINKV;
        float h = (d > 0.f) ? d * a / (d + EPSV) : 0.f;
        g_S[idx] = h;
        lsum += h;
    }
    __shared__ float red[256];
    red[threadIdx.x] = lsum;
    __syncthreads();
    for (int s = 128; s > 0; s >>= 1) {
        if (threadIdx.x < s) red[threadIdx.x] += red[threadIdx.x + s];
        __syncthreads();
    }
    if (threadIdx.x == 0) atomicAdd(&g_l1[m], red[0]);
}

// ---------------- K3: add_mem_raw[m][c] += sum_t h[m][t]*q[t][c] ----------------
// grid: (4 c-tiles of 64, 64 t-chunks of 1024); 256 threads, 8x4 micro-tile
__global__ __launch_bounds__(256) void k3_addmem(const float* __restrict__ q) {
    __shared__ float Hs[16][132];  // Hs[k][m]
    __shared__ float Qs[16][68];   // Qs[k][c]
    int tid = threadIdx.x;
    int tx = tid & 15, ty = tid >> 4;
    int c0 = blockIdx.x * 64;
    int tbase = blockIdx.y * 1024;

    float acc[8][4];
#pragma unroll
    for (int i = 0; i < 8; i++)
#pragma unroll
        for (int j = 0; j < 4; j++) acc[i][j] = 0.f;

    int lm = tid >> 1;
    int kb = (tid & 1) * 8;
    int kq = tid >> 4;
    int cq = (tid & 15) * 4;

    for (int kt = 0; kt < 1024; kt += 16) {
#pragma unroll
        for (int u = 0; u < 8; u++)
            Hs[kb + u][lm] = g_S[(size_t)lm * T_TOT + tbase + kt + kb + u];
#pragma unroll
        for (int u = 0; u < 4; u++)
            Qs[kq][cq + u] = q[(size_t)(tbase + kt + kq) * C_DIM + c0 + cq + u];
        __syncthreads();
#pragma unroll
        for (int k = 0; k < 16; k++) {
            float a[8], b[4];
#pragma unroll
            for (int i = 0; i < 8; i++) a[i] = Hs[k][ty + i * 16];
#pragma unroll
            for (int j = 0; j < 4; j++) b[j] = Qs[k][tx + j * 16];
#pragma unroll
            for (int i = 0; i < 8; i++)
#pragma unroll
                for (int j = 0; j < 4; j++) acc[i][j] += a[i] * b[j];
        }
        __syncthreads();
    }
#pragma unroll
    for (int i = 0; i < 8; i++)
#pragma unroll
        for (int j = 0; j < 4; j++)
            atomicAdd(&g_addmem[(ty + i * 16) * C_DIM + c0 + tx + j * 16], acc[i][j]);
}

// ---------------- K4: gate + new_mem (l1 normalization of add_mem folded here) ---------
__global__ __launch_bounds__(256) void k4_gate(const float* __restrict__ mem,
                                               const float* __restrict__ Uw,
                                               const float* __restrict__ Ub,
                                               const float* __restrict__ Ww,
                                               const float* __restrict__ Wb,
                                               float* __restrict__ nm_out) {
    int m = blockIdx.x;
    int c = threadIdx.x;
    __shared__ float mr[256], ar[256];
    float invl1 = 1.0f / fmaxf(g_l1[m], EPSV);
    mr[c] = mem[m * C_DIM + c];
    ar[c] = g_addmem[m * C_DIM + c] * invl1;
    __syncthreads();
    float s = Ub[c] + Wb[c];
#pragma unroll 4
    for (int k = 0; k < C_DIM; k++)
        s += mr[k] * Uw[c * C_DIM + k] + ar[k] * Ww[c * C_DIM + k];
    float g = 1.f / (1.f + __expf(-s));
    float nm = (1.f - g) * mr[c] + g * ar[c];
    g_newmem[m * C_DIM + c] = nm;
    nm_out[m * C_DIM + c] = nm;
}

// ---------------- K5: fused read phase ----------------
// per block: 64 tokens; smem holds new_mem (128x256), q tile, score tile.
__global__ __launch_bounds__(512) void k5_read(const float* __restrict__ q,
                                               float* __restrict__ out,
                                               float* __restrict__ attn) {
    extern __shared__ float sm[];
    float* nm = sm;                      // [128][257]
    float* qs = nm + 128 * 257;          // [64][256]
    float* ss = qs + 64 * 256;           // [64][132]

    int tid = threadIdx.x;
    int t0 = blockIdx.x * 64;

    for (int l = tid; l < 128 * 256; l += 512) {
        int m = l >> 8, k = l & 255;
        nm[m * 257 + k] = g_newmem[l];
    }
    for (int l = tid; l < 64 * 256; l += 512)
        qs[l] = q[(size_t)t0 * C_DIM + l];
    __syncthreads();

    int tx = tid & 15;          // m/c index base
    int ty = tid >> 4;          // 0..31 token base
    // ---- scores: 64t x 128m, 2x8 per thread ----
    {
        float acc[2][8];
#pragma unroll
        for (int i = 0; i < 2; i++)
#pragma unroll
            for (int j = 0; j < 8; j++) acc[i][j] = 0.f;
        for (int k = 0; k < C_DIM; k++) {
            float a0 = qs[ty * 256 + k];
            float a1 = qs[(ty + 32) * 256 + k];
            float b[8];
#pragma unroll
            for (int j = 0; j < 8; j++) b[j] = nm[(tx + j * 16) * 257 + k];
#pragma unroll
            for (int j = 0; j < 8; j++) {
                acc[0][j] += a0 * b[j];
                acc[1][j] += a1 * b[j];
            }
        }
#pragma unroll
        for (int i = 0; i < 2; i++)
#pragma unroll
            for (int j = 0; j < 8; j++)
                ss[(ty + i * 32) * 132 + tx + j * 16] = acc[i][j];
    }
    __syncthreads();

    // ---- softmax + hardshrink + l1-normalize per token row ----
    int warp = tid >> 5, lane = tid & 31;
    for (int r = 0; r < 4; r++) {
        int t = warp * 4 + r;
        float v[4];
#pragma unroll
        for (int k = 0; k < 4; k++) v[k] = ss[t * 132 + lane + k * 32];
        float mx = fmaxf(fmaxf(v[0], v[1]), fmaxf(v[2], v[3]));
#pragma unroll
        for (int o = 16; o > 0; o >>= 1)
            mx = fmaxf(mx, __shfl_xor_sync(0xffffffffu, mx, o));
        float e[4], sum = 0.f;
#pragma unroll
        for (int k = 0; k < 4; k++) { e[k] = __expf(v[k] - mx); sum += e[k]; }
#pragma unroll
        for (int o = 16; o > 0; o >>= 1)
            sum += __shfl_xor_sync(0xffffffffu, sum, o);
        float invs = 1.f / sum;
        float h[4], l1 = 0.f;
#pragma unroll
        for (int k = 0; k < 4; k++) {
            float a = e[k] * invs;
            float d = a - SHRINKV;
            h[k] = (d > 0.f) ? d * a / (d + EPSV) : 0.f;
            l1 += h[k];
        }
#pragma unroll
        for (int o = 16; o > 0; o >>= 1)
            l1 += __shfl_xor_sync(0xffffffffu, l1, o);
        float invl = 1.f / fmaxf(l1, EPSV);
#pragma unroll
        for (int k = 0; k < 4; k++) {
            h[k] *= invl;
            ss[t * 132 + lane + k * 32] = h[k];
            attn[(size_t)(t0 + t) * M_DIM + lane + k * 32] = h[k];
        }
    }
    __syncthreads();

    // ---- add_memory: 64t x 256c, 2x16 per thread ----
    {
        float acc[2][16];
#pragma unroll
        for (int i = 0; i < 2; i++)
#pragma unroll
            for (int j = 0; j < 16; j++) acc[i][j] = 0.f;
        for (int m = 0; m < M_DIM; m++) {
            float a0 = ss[ty * 132 + m];
            float a1 = ss[(ty + 32) * 132 + m];
            float b[16];
#pragma unroll
            for (int j = 0; j < 16; j++) b[j] = nm[m * 257 + tx + j * 16];
#pragma unroll
            for (int j = 0; j < 16; j++) {
                acc[0][j] += a0 * b[j];
                acc[1][j] += a1 * b[j];
            }
        }
#pragma unroll
        for (int i = 0; i < 2; i++)
#pragma unroll
            for (int j = 0; j < 16; j++)
                out[(size_t)(t0 + ty + i * 32) * 512 + 256 + tx + j * 16] = acc[i][j];
    }
    // copy q into first 256 cols
    for (int l = tid; l < 64 * 256; l += 512) {
        int t = l >> 8, c = l & 255;
        out[(size_t)(t0 + t) * 512 + c] = qs[l];
    }
}

// ---------------- launcher ----------------
extern "C" void kernel_launch(void* const* d_in, const int* in_sizes, int n_in,
                              void* d_out, int out_size) {
    const float* query = (const float*)d_in[0];  // (64,1024,256)
    const float* mem   = (const float*)d_in[1];  // (128,256)
    const float* Uw    = (const float*)d_in[2];  // (256,256)
    const float* Ub    = (const float*)d_in[3];  // (256,)
    const float* Ww    = (const float*)d_in[4];  // (256,256)
    const float* Wb    = (const float*)d_in[5];  // (256,)

    float* out  = (float*)d_out;                 // (T,512)
    float* attn = out + (size_t)T_TOT * 512;     // (T,128)
    float* nmo  = attn + (size_t)T_TOT * M_DIM;  // (128,256)

    const int SMEM5 = (128 * 257 + 64 * 256 + 64 * 132) * 4; // 230912 B
    cudaFuncSetAttribute(k5_read, cudaFuncAttributeMaxDynamicSharedMemorySize, SMEM5);

    k0_init<<<128, 256>>>();
    k1_scores<<<T_TOT / 128, 256>>>(query, mem);
    k2_shrink<<<dim3(32, 128), 256>>>();
    k3_addmem<<<dim3(4, 64), 256>>>(query);
    k4_gate<<<128, 256>>>(mem, Uw, Ub, Ww, Wb, nmo);
    k5_read<<<T_TOT / 64, 512, SMEM5>>>(query, out, attn);
}

// round 5
// speedup vs baseline: 1.3474x; 1.3474x over previous
#include <cuda_runtime.h>
#include <cstdint>
#include <math.h>

#define T_TOT 65536
#define C_DIM 256
#define M_DIM 128
#define SHRINKV 0.0025f
#define EPSV 1e-12f
#define LIST_CAP 4194304

// ---------------- scratch ----------------
__device__ float g_S[(size_t)M_DIM * T_TOT];   // 33.5 MB: exp(scores), layout [m][t]
__device__ float g_rowsum[M_DIM];
__device__ float g_l1[M_DIM];
__device__ float g_addmem[M_DIM * C_DIM];
__device__ float g_newmem[M_DIM * C_DIM];
__device__ unsigned int g_cnt;
__device__ unsigned int g_key[LIST_CAP];       // (t<<7)|m
__device__ float g_val[LIST_CAP];              // a, then h

// ---------------- K0: zero accumulators ----------------
__global__ void k0_init() {
    int i = blockIdx.x * blockDim.x + threadIdx.x;
    if (i < M_DIM) { g_rowsum[i] = 0.f; g_l1[i] = 0.f; }
    if (i < M_DIM * C_DIM) g_addmem[i] = 0.f;
    if (i == 0) g_cnt = 0u;
}

// ---------------- K1: S[m][t] = exp(mem[m].q[t]); rowsum[m] += ... ----------------
// (proven R2 kernel: 128t x 128m tile, 256 threads, 8x8 micro-tile)
__global__ __launch_bounds__(256) void k1_scores(const float* __restrict__ q,
                                                 const float* __restrict__ mem) {
    __shared__ float As[16][132];   // As[k][m]
    __shared__ float Bs[16][132];   // Bs[k][t]
    __shared__ float rsum[128];

    int tid = threadIdx.x;
    int tx = tid & 15, ty = tid >> 4;
    int t0 = blockIdx.x * 128;

    float acc[8][8];
#pragma unroll
    for (int i = 0; i < 8; i++)
#pragma unroll
        for (int j = 0; j < 8; j++) acc[i][j] = 0.f;

    int lm = tid >> 1;
    int kb = (tid & 1) * 8;

    for (int k0 = 0; k0 < C_DIM; k0 += 16) {
#pragma unroll
        for (int u = 0; u < 8; u++)
            As[kb + u][lm] = mem[lm * C_DIM + k0 + kb + u];
#pragma unroll
        for (int u = 0; u < 8; u++)
            Bs[kb + u][lm] = q[(size_t)(t0 + lm) * C_DIM + k0 + kb + u];
        __syncthreads();
#pragma unroll
        for (int k = 0; k < 16; k++) {
            float a[8], b[8];
#pragma unroll
            for (int i = 0; i < 8; i++) a[i] = As[k][ty + i * 16];
#pragma unroll
            for (int j = 0; j < 8; j++) b[j] = Bs[k][tx + j * 16];
#pragma unroll
            for (int i = 0; i < 8; i++)
#pragma unroll
                for (int j = 0; j < 8; j++) acc[i][j] += a[i] * b[j];
        }
        __syncthreads();
    }

    if (tid < 128) rsum[tid] = 0.f;
    __syncthreads();

#pragma unroll
    for (int i = 0; i < 8; i++) {
        float part = 0.f;
        int m = ty + i * 16;
#pragma unroll
        for (int j = 0; j < 8; j++) {
            float e = __expf(acc[i][j]);
            part += e;
            g_S[(size_t)m * T_TOT + t0 + tx + j * 16] = e;
        }
        atomicAdd(&rsum[m], part);
    }
    __syncthreads();
    if (tid < 128) atomicAdd(&g_rowsum[tid], rsum[tid]);
}

// ---------------- K2: scan S for survivors of hard-shrink (a > SHRINK) ----------------
// grid: (4 t-chunks of 16384, 128 m); coalesced float4 reads along t.
__global__ __launch_bounds__(256) void k2_scan() {
    int m = blockIdx.y;
    float rs = g_rowsum[m];
    float thr = SHRINKV * rs;            // e > SHRINK*rowsum  <=>  a > SHRINK
    float inv = 1.0f / rs;
    size_t rowbase = (size_t)m * T_TOT;
    int tbase = blockIdx.x * 16384 + threadIdx.x * 4;
#pragma unroll
    for (int j = 0; j < 16; j++) {
        int t = tbase + j * 1024;
        float4 v = *(const float4*)&g_S[rowbase + t];
        float e[4] = {v.x, v.y, v.z, v.w};
#pragma unroll
        for (int k = 0; k < 4; k++) {
            if (e[k] > thr) {
                unsigned int pos = atomicAdd(&g_cnt, 1u);
                if (pos < LIST_CAP) {
                    g_key[pos] = ((unsigned int)(t + k) << 7) | (unsigned int)m;
                    g_val[pos] = e[k] * inv;
                }
            }
        }
    }
}

// ---------------- K3a: h = shrink(a), l1[m] += h ----------------
__global__ __launch_bounds__(256) void k3_l1() {
    unsigned int n = g_cnt; if (n > LIST_CAP) n = LIST_CAP;
    for (unsigned int i = blockIdx.x * 256 + threadIdx.x; i < n; i += gridDim.x * 256) {
        float a = g_val[i];
        float d = a - SHRINKV;
        float h = (d > 0.f) ? d * a / (d + EPSV) : 0.f;
        g_val[i] = h;
        atomicAdd(&g_l1[g_key[i] & 127], h);
    }
}

// ---------------- K3b: add_mem[m][c] += h * q[t][c] ----------------
__global__ __launch_bounds__(256) void k3_scatter(const float* __restrict__ q) {
    unsigned int n = g_cnt; if (n > LIST_CAP) n = LIST_CAP;
    int c = threadIdx.x;
    for (unsigned int i = blockIdx.x; i < n; i += gridDim.x) {
        unsigned int key = g_key[i];
        unsigned int t = key >> 7, m = key & 127;
        float h = g_val[i];
        atomicAdd(&g_addmem[m * C_DIM + c], h * q[(size_t)t * C_DIM + c]);
    }
}

// ---------------- K4: gate + new_mem (l1 normalize folded) ----------------
__global__ __launch_bounds__(256) void k4_gate(const float* __restrict__ mem,
                                               const float* __restrict__ Uw,
                                               const float* __restrict__ Ub,
                                               const float* __restrict__ Ww,
                                               const float* __restrict__ Wb,
                                               float* __restrict__ nm_out) {
    int m = blockIdx.x;
    int c = threadIdx.x;
    __shared__ float mr[256], ar[256];
    float invl1 = 1.0f / fmaxf(g_l1[m], EPSV);
    mr[c] = mem[m * C_DIM + c];
    ar[c] = g_addmem[m * C_DIM + c] * invl1;
    __syncthreads();
    float s = Ub[c] + Wb[c];
#pragma unroll 4
    for (int k = 0; k < C_DIM; k++)
        s += mr[k] * Uw[c * C_DIM + k] + ar[k] * Ww[c * C_DIM + k];
    float g = 1.f / (1.f + __expf(-s));
    float nm = (1.f - g) * mr[c] + g * ar[c];
    g_newmem[m * C_DIM + c] = nm;
    nm_out[m * C_DIM + c] = nm;
}

// ---------------- K5: fused read phase (proven) ----------------
__global__ __launch_bounds__(512) void k5_read(const float* __restrict__ q,
                                               float* __restrict__ out,
                                               float* __restrict__ attn) {
    extern __shared__ float sm[];
    float* nm = sm;                      // [128][257]
    float* qs = nm + 128 * 257;          // [64][256]
    float* ss = qs + 64 * 256;           // [64][132]

    int tid = threadIdx.x;
    int t0 = blockIdx.x * 64;

    for (int l = tid; l < 128 * 256; l += 512) {
        int m = l >> 8, k = l & 255;
        nm[m * 257 + k] = g_newmem[l];
    }
    for (int l = tid; l < 64 * 256; l += 512)
        qs[l] = q[(size_t)t0 * C_DIM + l];
    __syncthreads();

    int tx = tid & 15;
    int ty = tid >> 4;
    {
        float acc[2][8];
#pragma unroll
        for (int i = 0; i < 2; i++)
#pragma unroll
            for (int j = 0; j < 8; j++) acc[i][j] = 0.f;
        for (int k = 0; k < C_DIM; k++) {
            float a0 = qs[ty * 256 + k];
            float a1 = qs[(ty + 32) * 256 + k];
            float b[8];
#pragma unroll
            for (int j = 0; j < 8; j++) b[j] = nm[(tx + j * 16) * 257 + k];
#pragma unroll
            for (int j = 0; j < 8; j++) {
                acc[0][j] += a0 * b[j];
                acc[1][j] += a1 * b[j];
            }
        }
#pragma unroll
        for (int i = 0; i < 2; i++)
#pragma unroll
            for (int j = 0; j < 8; j++)
                ss[(ty + i * 32) * 132 + tx + j * 16] = acc[i][j];
    }
    __syncthreads();

    int warp = tid >> 5, lane = tid & 31;
    for (int r = 0; r < 4; r++) {
        int t = warp * 4 + r;
        float v[4];
#pragma unroll
        for (int k = 0; k < 4; k++) v[k] = ss[t * 132 + lane + k * 32];
        float mx = fmaxf(fmaxf(v[0], v[1]), fmaxf(v[2], v[3]));
#pragma unroll
        for (int o = 16; o > 0; o >>= 1)
            mx = fmaxf(mx, __shfl_xor_sync(0xffffffffu, mx, o));
        float e[4], sum = 0.f;
#pragma unroll
        for (int k = 0; k < 4; k++) { e[k] = __expf(v[k] - mx); sum += e[k]; }
#pragma unroll
        for (int o = 16; o > 0; o >>= 1)
            sum += __shfl_xor_sync(0xffffffffu, sum, o);
        float invs = 1.f / sum;
        float h[4], l1 = 0.f;
#pragma unroll
        for (int k = 0; k < 4; k++) {
            float a = e[k] * invs;
            float d = a - SHRINKV;
            h[k] = (d > 0.f) ? d * a / (d + EPSV) : 0.f;
            l1 += h[k];
        }
#pragma unroll
        for (int o = 16; o > 0; o >>= 1)
            l1 += __shfl_xor_sync(0xffffffffu, l1, o);
        float invl = 1.f / fmaxf(l1, EPSV);
#pragma unroll
        for (int k = 0; k < 4; k++) {
            h[k] *= invl;
            ss[t * 132 + lane + k * 32] = h[k];
            attn[(size_t)(t0 + t) * M_DIM + lane + k * 32] = h[k];
        }
    }
    __syncthreads();

    {
        float acc[2][16];
#pragma unroll
        for (int i = 0; i < 2; i++)
#pragma unroll
            for (int j = 0; j < 16; j++) acc[i][j] = 0.f;
        for (int m = 0; m < M_DIM; m++) {
            float a0 = ss[ty * 132 + m];
            float a1 = ss[(ty + 32) * 132 + m];
            float b[16];
#pragma unroll
            for (int j = 0; j < 16; j++) b[j] = nm[m * 257 + tx + j * 16];
#pragma unroll
            for (int j = 0; j < 16; j++) {
                acc[0][j] += a0 * b[j];
                acc[1][j] += a1 * b[j];
            }
        }
#pragma unroll
        for (int i = 0; i < 2; i++)
#pragma unroll
            for (int j = 0; j < 16; j++)
                out[(size_t)(t0 + ty + i * 32) * 512 + 256 + tx + j * 16] = acc[i][j];
    }
    for (int l = tid; l < 64 * 256; l += 512) {
        int t = l >> 8, c = l & 255;
        out[(size_t)(t0 + t) * 512 + c] = qs[l];
    }
}

// ---------------- launcher ----------------
extern "C" void kernel_launch(void* const* d_in, const int* in_sizes, int n_in,
                              void* d_out, int out_size) {
    const float* query = (const float*)d_in[0];
    const float* mem   = (const float*)d_in[1];
    const float* Uw    = (const float*)d_in[2];
    const float* Ub    = (const float*)d_in[3];
    const float* Ww    = (const float*)d_in[4];
    const float* Wb    = (const float*)d_in[5];

    float* out  = (float*)d_out;
    float* attn = out + (size_t)T_TOT * 512;
    float* nmo  = attn + (size_t)T_TOT * M_DIM;

    const int SMEM5 = (128 * 257 + 64 * 256 + 64 * 132) * 4;
    cudaFuncSetAttribute(k5_read, cudaFuncAttributeMaxDynamicSharedMemorySize, SMEM5);

    k0_init<<<128, 256>>>();
    k1_scores<<<T_TOT / 128, 256>>>(query, mem);
    k2_scan<<<dim3(4, 128), 256>>>();
    k3_l1<<<16, 256>>>();
    k3_scatter<<<64, 256>>>(query);
    k4_gate<<<128, 256>>>(mem, Uw, Ub, Ww, Wb, nmo);
    k5_read<<<T_TOT / 64, 512, SMEM5>>>(query, out, attn);
}

// round 6
// speedup vs baseline: 1.4031x; 1.0413x over previous
#include <cuda_runtime.h>
#include <cstdint>
#include <math.h>

#define T_TOT 65536
#define C_DIM 256
#define M_DIM 128
#define SHRINKV 0.0025f
#define EPSV 1e-12f
#define LIST_CAP 4194304

typedef unsigned long long ull;

// packed fp32x2 helpers (Blackwell base-family PTX, compiles at compute_103)
__device__ __forceinline__ ull pk2(float lo, float hi) {
    ull r; asm("mov.b64 %0, {%1, %2};" : "=l"(r) : "f"(lo), "f"(hi)); return r;
}
__device__ __forceinline__ void upk2(float& lo, float& hi, ull v) {
    asm("mov.b64 {%0, %1}, %2;" : "=f"(lo), "=f"(hi) : "l"(v));
}
#define FMA2(acc, a, b) asm("fma.rn.f32x2 %0, %1, %2, %0;" : "+l"(acc) : "l"(a), "l"(b))

// ---------------- scratch ----------------
__device__ float g_S[(size_t)M_DIM * T_TOT];   // exp(scores), layout [m][t]
__device__ float g_rowsum[M_DIM];
__device__ float g_l1[M_DIM];
__device__ float g_addmem[M_DIM * C_DIM];
__device__ float g_newmem[M_DIM * C_DIM];
__device__ unsigned int g_cnt;
__device__ unsigned int g_key[LIST_CAP];
__device__ float g_val[LIST_CAP];

// ---------------- K0 ----------------
__global__ void k0_init() {
    int i = blockIdx.x * blockDim.x + threadIdx.x;
    if (i < M_DIM) { g_rowsum[i] = 0.f; g_l1[i] = 0.f; }
    if (i < M_DIM * C_DIM) g_addmem[i] = 0.f;
    if (i == 0) g_cnt = 0u;
}

// ---------------- K1: S[m][t] = exp(mem[m].q[t]); rowsum ----------------
// 128t x 128m tile, 512 threads, packed-k FMA2, 4x8 micro-tile (i->m, j->t)
__global__ __launch_bounds__(512) void k1_scores(const float* __restrict__ q,
                                                 const float* __restrict__ mem) {
    __shared__ float Am[128 * 18];   // Am[m][k] chunk of 16 k
    __shared__ float Bt[128 * 18];   // Bt[t][k]
    __shared__ float rsum[128];

    int tid = threadIdx.x;
    int tx = tid & 15;        // t = tx + j*16
    int ty = tid >> 4;        // m = ty + i*32
    int t0 = blockIdx.x * 128;

    ull acc2[4][8];
#pragma unroll
    for (int i = 0; i < 4; i++)
#pragma unroll
        for (int j = 0; j < 8; j++) acc2[i][j] = 0ull;

    int lr = tid >> 2;            // 0..127 row
    int kb = (tid & 3) * 4;       // 0,4,8,12

    for (int k0 = 0; k0 < C_DIM; k0 += 16) {
        {
            float4 va = *(const float4*)&mem[lr * C_DIM + k0 + kb];
            Am[lr * 18 + kb + 0] = va.x; Am[lr * 18 + kb + 1] = va.y;
            Am[lr * 18 + kb + 2] = va.z; Am[lr * 18 + kb + 3] = va.w;
            float4 vb = *(const float4*)&q[(size_t)(t0 + lr) * C_DIM + k0 + kb];
            Bt[lr * 18 + kb + 0] = vb.x; Bt[lr * 18 + kb + 1] = vb.y;
            Bt[lr * 18 + kb + 2] = vb.z; Bt[lr * 18 + kb + 3] = vb.w;
        }
        __syncthreads();
#pragma unroll
        for (int k = 0; k < 16; k += 2) {
            ull pa[4], pb[8];
#pragma unroll
            for (int i = 0; i < 4; i++)
                pa[i] = *(const ull*)&Am[(ty + i * 32) * 18 + k];
#pragma unroll
            for (int j = 0; j < 8; j++)
                pb[j] = *(const ull*)&Bt[(tx + j * 16) * 18 + k];
#pragma unroll
            for (int i = 0; i < 4; i++)
#pragma unroll
                for (int j = 0; j < 8; j++) FMA2(acc2[i][j], pa[i], pb[j]);
        }
        __syncthreads();
    }

    if (tid < 128) rsum[tid] = 0.f;
    __syncthreads();

#pragma unroll
    for (int i = 0; i < 4; i++) {
        int m = ty + i * 32;
        float part = 0.f;
#pragma unroll
        for (int j = 0; j < 8; j++) {
            float lo, hi;
            upk2(lo, hi, acc2[i][j]);
            float e = __expf(lo + hi);
            part += e;
            g_S[(size_t)m * T_TOT + t0 + tx + j * 16] = e;
        }
        atomicAdd(&rsum[m], part);
    }
    __syncthreads();
    if (tid < 128) atomicAdd(&g_rowsum[tid], rsum[tid]);
}

// ---------------- K2: scan survivors (a > SHRINK) ----------------
__global__ __launch_bounds__(256) void k2_scan() {
    int m = blockIdx.y;
    float rs = g_rowsum[m];
    float thr = SHRINKV * rs;
    float inv = 1.0f / rs;
    size_t rowbase = (size_t)m * T_TOT;
    int tbase = blockIdx.x * 16384 + threadIdx.x * 4;
#pragma unroll
    for (int j = 0; j < 16; j++) {
        int t = tbase + j * 1024;
        float4 v = *(const float4*)&g_S[rowbase + t];
        float e[4] = {v.x, v.y, v.z, v.w};
#pragma unroll
        for (int k = 0; k < 4; k++) {
            if (e[k] > thr) {
                unsigned int pos = atomicAdd(&g_cnt, 1u);
                if (pos < LIST_CAP) {
                    g_key[pos] = ((unsigned int)(t + k) << 7) | (unsigned int)m;
                    g_val[pos] = e[k] * inv;
                }
            }
        }
    }
}

// ---------------- K3a ----------------
__global__ __launch_bounds__(256) void k3_l1() {
    unsigned int n = g_cnt; if (n > LIST_CAP) n = LIST_CAP;
    for (unsigned int i = blockIdx.x * 256 + threadIdx.x; i < n; i += gridDim.x * 256) {
        float a = g_val[i];
        float d = a - SHRINKV;
        float h = (d > 0.f) ? d * a / (d + EPSV) : 0.f;
        g_val[i] = h;
        atomicAdd(&g_l1[g_key[i] & 127], h);
    }
}

// ---------------- K3b ----------------
__global__ __launch_bounds__(256) void k3_scatter(const float* __restrict__ q) {
    unsigned int n = g_cnt; if (n > LIST_CAP) n = LIST_CAP;
    int c = threadIdx.x;
    for (unsigned int i = blockIdx.x; i < n; i += gridDim.x) {
        unsigned int key = g_key[i];
        unsigned int t = key >> 7, m = key & 127;
        float h = g_val[i];
        atomicAdd(&g_addmem[m * C_DIM + c], h * q[(size_t)t * C_DIM + c]);
    }
}

// ---------------- K4: gate + new_mem ----------------
__global__ __launch_bounds__(256) void k4_gate(const float* __restrict__ mem,
                                               const float* __restrict__ Uw,
                                               const float* __restrict__ Ub,
                                               const float* __restrict__ Ww,
                                               const float* __restrict__ Wb,
                                               float* __restrict__ nm_out) {
    int m = blockIdx.x;
    int c = threadIdx.x;
    __shared__ float mr[256], ar[256];
    float invl1 = 1.0f / fmaxf(g_l1[m], EPSV);
    mr[c] = mem[m * C_DIM + c];
    ar[c] = g_addmem[m * C_DIM + c] * invl1;
    __syncthreads();
    float s = Ub[c] + Wb[c];
#pragma unroll 4
    for (int k = 0; k < C_DIM; k++)
        s += mr[k] * Uw[c * C_DIM + k] + ar[k] * Ww[c * C_DIM + k];
    float g = 1.f / (1.f + __expf(-s));
    float nm = (1.f - g) * mr[c] + g * ar[c];
    g_newmem[m * C_DIM + c] = nm;
    nm_out[m * C_DIM + c] = nm;
}

// ---------------- K5: fused read phase, packed FMA2 ----------------
// 512 threads, 64 tokens/block. nm padded to 258 (k-pairs 8B aligned).
#define NM_P 258
#define SS_P 130
__global__ __launch_bounds__(512) void k5_read(const float* __restrict__ q,
                                               float* __restrict__ out,
                                               float* __restrict__ attn) {
    extern __shared__ float sm[];
    float* nm = sm;                       // [128][258]
    float* qs = nm + 128 * NM_P;          // [64][256]
    float* ss = qs + 64 * 256;            // [64][130]

    int tid = threadIdx.x;
    int t0 = blockIdx.x * 64;

    for (int l = tid; l < 128 * 256; l += 512) {
        int m = l >> 8, k = l & 255;
        nm[m * NM_P + k] = g_newmem[l];
    }
    for (int l = tid; l < 64 * 256; l += 512)
        qs[l] = q[(size_t)t0 * C_DIM + l];
    __syncthreads();

    int tx = tid & 15;          // scores: m = tx + j*16 ; add: c-pair = tx*2 + j*32
    int ty = tid >> 4;          // t = ty, ty+32

    // ---- scores GEMM: pack along k (reduction) ----
    {
        ull acc2[2][8];
#pragma unroll
        for (int i = 0; i < 2; i++)
#pragma unroll
            for (int j = 0; j < 8; j++) acc2[i][j] = 0ull;

        for (int k = 0; k < C_DIM; k += 2) {
            ull pa0 = *(const ull*)&qs[ty * 256 + k];
            ull pa1 = *(const ull*)&qs[(ty + 32) * 256 + k];
            ull pb[8];
#pragma unroll
            for (int j = 0; j < 8; j++)
                pb[j] = *(const ull*)&nm[(tx + j * 16) * NM_P + k];
#pragma unroll
            for (int j = 0; j < 8; j++) {
                FMA2(acc2[0][j], pa0, pb[j]);
                FMA2(acc2[1][j], pa1, pb[j]);
            }
        }
#pragma unroll
        for (int i = 0; i < 2; i++)
#pragma unroll
            for (int j = 0; j < 8; j++) {
                float lo, hi;
                upk2(lo, hi, acc2[i][j]);
                ss[(ty + i * 32) * SS_P + tx + j * 16] = lo + hi;
            }
    }
    __syncthreads();

    // ---- softmax + hardshrink + l1-normalize per token ----
    int warp = tid >> 5, lane = tid & 31;
    for (int r = 0; r < 4; r++) {
        int t = warp * 4 + r;
        float v[4];
#pragma unroll
        for (int k = 0; k < 4; k++) v[k] = ss[t * SS_P + lane + k * 32];
        float mx = fmaxf(fmaxf(v[0], v[1]), fmaxf(v[2], v[3]));
#pragma unroll
        for (int o = 16; o > 0; o >>= 1)
            mx = fmaxf(mx, __shfl_xor_sync(0xffffffffu, mx, o));
        float e[4], sum = 0.f;
#pragma unroll
        for (int k = 0; k < 4; k++) { e[k] = __expf(v[k] - mx); sum += e[k]; }
#pragma unroll
        for (int o = 16; o > 0; o >>= 1)
            sum += __shfl_xor_sync(0xffffffffu, sum, o);
        float invs = 1.f / sum;
        float h[4], l1 = 0.f;
#pragma unroll
        for (int k = 0; k < 4; k++) {
            float a = e[k] * invs;
            float d = a - SHRINKV;
            h[k] = (d > 0.f) ? d * a / (d + EPSV) : 0.f;
            l1 += h[k];
        }
#pragma unroll
        for (int o = 16; o > 0; o >>= 1)
            l1 += __shfl_xor_sync(0xffffffffu, l1, o);
        float invl = 1.f / fmaxf(l1, EPSV);
#pragma unroll
        for (int k = 0; k < 4; k++) {
            h[k] *= invl;
            ss[t * SS_P + lane + k * 32] = h[k];
            attn[(size_t)(t0 + t) * M_DIM + lane + k * 32] = h[k];
        }
    }
    __syncthreads();

    // ---- add_memory GEMM: pack along c (output), broadcast a ----
    {
        ull acc2[2][8];
#pragma unroll
        for (int i = 0; i < 2; i++)
#pragma unroll
            for (int j = 0; j < 8; j++) acc2[i][j] = 0ull;

        for (int m = 0; m < M_DIM; m++) {
            float a0 = ss[ty * SS_P + m];
            float a1 = ss[(ty + 32) * SS_P + m];
            ull pa0 = pk2(a0, a0);
            ull pa1 = pk2(a1, a1);
            ull pb[8];
#pragma unroll
            for (int j = 0; j < 8; j++)
                pb[j] = *(const ull*)&nm[m * NM_P + tx * 2 + j * 32];
#pragma unroll
            for (int j = 0; j < 8; j++) {
                FMA2(acc2[0][j], pa0, pb[j]);
                FMA2(acc2[1][j], pa1, pb[j]);
            }
        }
#pragma unroll
        for (int i = 0; i < 2; i++) {
            int t = t0 + ty + i * 32;
#pragma unroll
            for (int j = 0; j < 8; j++)
                *(ull*)&out[(size_t)t * 512 + 256 + tx * 2 + j * 32] = acc2[i][j];
        }
    }
    // copy q into first 256 cols
    for (int l = tid; l < 64 * 256; l += 512) {
        int t = l >> 8, c = l & 255;
        out[(size_t)(t0 + t) * 512 + c] = qs[l];
    }
}

// ---------------- launcher ----------------
extern "C" void kernel_launch(void* const* d_in, const int* in_sizes, int n_in,
                              void* d_out, int out_size) {
    const float* query = (const float*)d_in[0];
    const float* mem   = (const float*)d_in[1];
    const float* Uw    = (const float*)d_in[2];
    const float* Ub    = (const float*)d_in[3];
    const float* Ww    = (const float*)d_in[4];
    const float* Wb    = (const float*)d_in[5];

    float* out  = (float*)d_out;
    float* attn = out + (size_t)T_TOT * 512;
    float* nmo  = attn + (size_t)T_TOT * M_DIM;

    const int SMEM5 = (128 * NM_P + 64 * 256 + 64 * SS_P) * 4;  // 230,912 B
    cudaFuncSetAttribute(k5_read, cudaFuncAttributeMaxDynamicSharedMemorySize, SMEM5);

    k0_init<<<128, 256>>>();
    k1_scores<<<T_TOT / 128, 512>>>(query, mem);
    k2_scan<<<dim3(4, 128), 256>>>();
    k3_l1<<<16, 256>>>();
    k3_scatter<<<64, 256>>>(query);
    k4_gate<<<128, 256>>>(mem, Uw, Ub, Ww, Wb, nmo);
    k5_read<<<T_TOT / 64, 512, SMEM5>>>(query, out, attn);
}

// round 7
// speedup vs baseline: 1.4711x; 1.0485x over previous
#include <cuda_runtime.h>
#include <cstdint>
#include <math.h>

#define T_TOT 65536
#define C_DIM 256
#define M_DIM 128
#define SHRINKV 0.0025f
#define EPSV 1e-12f
#define LIST_CAP 4194304

typedef unsigned long long ull;

__device__ __forceinline__ ull pk2(float lo, float hi) {
    ull r; asm("mov.b64 %0, {%1, %2};" : "=l"(r) : "f"(lo), "f"(hi)); return r;
}
__device__ __forceinline__ void upk2(float& lo, float& hi, ull v) {
    asm("mov.b64 {%0, %1}, %2;" : "=f"(lo), "=f"(hi) : "l"(v));
}
#define FMA2(acc, a, b) asm("fma.rn.f32x2 %0, %1, %2, %0;" : "+l"(acc) : "l"(a), "l"(b))

// ---------------- scratch ----------------
__device__ float g_S[(size_t)M_DIM * T_TOT];   // exp(scores), [m][t]
__device__ float g_rowsum[M_DIM];
__device__ float g_l1[M_DIM];
__device__ float g_addmem[M_DIM * C_DIM];
__device__ float g_newmem[M_DIM * C_DIM];
__device__ unsigned int g_cnt;
__device__ unsigned int g_key[LIST_CAP];
__device__ float g_val[LIST_CAP];

// ---------------- K0 ----------------
__global__ void k0_init() {
    int i = blockIdx.x * blockDim.x + threadIdx.x;
    if (i < M_DIM) { g_rowsum[i] = 0.f; g_l1[i] = 0.f; }
    if (i < M_DIM * C_DIM) g_addmem[i] = 0.f;
    if (i == 0) g_cnt = 0u;
}

// ---------------- K1: S[m][t] = exp(mem[m].q[t]); rowsum ----------------
// 128t x 128m tile, 256 threads, 8m x 8t per thread, k-packed FMA2
__global__ __launch_bounds__(256) void k1_scores(const float* __restrict__ q,
                                                 const float* __restrict__ mem) {
    __shared__ float Am[128 * 18];   // Am[m][k16]
    __shared__ float Bt[128 * 18];   // Bt[t][k16]
    __shared__ float rsum[128];

    int tid = threadIdx.x;
    int tx = tid & 15;        // t = tx + j*16
    int ty = tid >> 4;        // m = ty + i*16
    int t0 = blockIdx.x * 128;

    ull acc2[8][8];
#pragma unroll
    for (int i = 0; i < 8; i++)
#pragma unroll
        for (int j = 0; j < 8; j++) acc2[i][j] = 0ull;

    int lr = tid >> 1;            // 0..127
    int kb = (tid & 1) * 8;       // 0 or 8

    for (int k0 = 0; k0 < C_DIM; k0 += 16) {
        {
            float4 a0 = *(const float4*)&mem[lr * C_DIM + k0 + kb];
            float4 a1 = *(const float4*)&mem[lr * C_DIM + k0 + kb + 4];
            Am[lr * 18 + kb + 0] = a0.x; Am[lr * 18 + kb + 1] = a0.y;
            Am[lr * 18 + kb + 2] = a0.z; Am[lr * 18 + kb + 3] = a0.w;
            Am[lr * 18 + kb + 4] = a1.x; Am[lr * 18 + kb + 5] = a1.y;
            Am[lr * 18 + kb + 6] = a1.z; Am[lr * 18 + kb + 7] = a1.w;
            float4 b0 = *(const float4*)&q[(size_t)(t0 + lr) * C_DIM + k0 + kb];
            float4 b1 = *(const float4*)&q[(size_t)(t0 + lr) * C_DIM + k0 + kb + 4];
            Bt[lr * 18 + kb + 0] = b0.x; Bt[lr * 18 + kb + 1] = b0.y;
            Bt[lr * 18 + kb + 2] = b0.z; Bt[lr * 18 + kb + 3] = b0.w;
            Bt[lr * 18 + kb + 4] = b1.x; Bt[lr * 18 + kb + 5] = b1.y;
            Bt[lr * 18 + kb + 6] = b1.z; Bt[lr * 18 + kb + 7] = b1.w;
        }
        __syncthreads();
#pragma unroll
        for (int k = 0; k < 16; k += 2) {
            ull pa[8], pb[8];
#pragma unroll
            for (int i = 0; i < 8; i++)
                pa[i] = *(const ull*)&Am[(ty + i * 16) * 18 + k];
#pragma unroll
            for (int j = 0; j < 8; j++)
                pb[j] = *(const ull*)&Bt[(tx + j * 16) * 18 + k];
#pragma unroll
            for (int i = 0; i < 8; i++)
#pragma unroll
                for (int j = 0; j < 8; j++) FMA2(acc2[i][j], pa[i], pb[j]);
        }
        __syncthreads();
    }

    if (tid < 128) rsum[tid] = 0.f;
    __syncthreads();

#pragma unroll
    for (int i = 0; i < 8; i++) {
        int m = ty + i * 16;
        float part = 0.f;
#pragma unroll
        for (int j = 0; j < 8; j++) {
            float lo, hi;
            upk2(lo, hi, acc2[i][j]);
            float e = __expf(lo + hi);
            part += e;
            g_S[(size_t)m * T_TOT + t0 + tx + j * 16] = e;
        }
        atomicAdd(&rsum[m], part);
    }
    __syncthreads();
    if (tid < 128) atomicAdd(&g_rowsum[tid], rsum[tid]);
}

// ---------------- K2: scan survivors + shrink + l1 (fused) ----------------
__global__ __launch_bounds__(256) void k2_scan() {
    int m = blockIdx.y;
    float rs = g_rowsum[m];
    float thr = SHRINKV * rs;            // e > SHRINK*rowsum <=> a > SHRINK
    float inv = 1.0f / rs;
    size_t rowbase = (size_t)m * T_TOT;
    int tbase = blockIdx.x * 16384 + threadIdx.x * 4;
#pragma unroll
    for (int j = 0; j < 16; j++) {
        int t = tbase + j * 1024;
        float4 v = *(const float4*)&g_S[rowbase + t];
        float e[4] = {v.x, v.y, v.z, v.w};
#pragma unroll
        for (int k = 0; k < 4; k++) {
            if (e[k] > thr) {
                float a = e[k] * inv;
                float d = a - SHRINKV;
                float h = (d > 0.f) ? d * a / (d + EPSV) : 0.f;
                unsigned int pos = atomicAdd(&g_cnt, 1u);
                if (pos < LIST_CAP) {
                    g_key[pos] = ((unsigned int)(t + k) << 7) | (unsigned int)m;
                    g_val[pos] = h;
                }
                atomicAdd(&g_l1[m], h);
            }
        }
    }
}

// ---------------- K3: add_mem[m][c] += h * q[t][c] ----------------
__global__ __launch_bounds__(256) void k3_scatter(const float* __restrict__ q) {
    unsigned int n = g_cnt; if (n > LIST_CAP) n = LIST_CAP;
    int c = threadIdx.x;
    for (unsigned int i = blockIdx.x; i < n; i += gridDim.x) {
        unsigned int key = g_key[i];
        unsigned int t = key >> 7, m = key & 127;
        float h = g_val[i];
        atomicAdd(&g_addmem[m * C_DIM + c], h * q[(size_t)t * C_DIM + c]);
    }
}

// ---------------- K4: gate + new_mem ----------------
__global__ __launch_bounds__(256) void k4_gate(const float* __restrict__ mem,
                                               const float* __restrict__ Uw,
                                               const float* __restrict__ Ub,
                                               const float* __restrict__ Ww,
                                               const float* __restrict__ Wb,
                                               float* __restrict__ nm_out) {
    int m = blockIdx.x;
    int c = threadIdx.x;
    __shared__ float mr[256], ar[256];
    float invl1 = 1.0f / fmaxf(g_l1[m], EPSV);
    mr[c] = mem[m * C_DIM + c];
    ar[c] = g_addmem[m * C_DIM + c] * invl1;
    __syncthreads();
    float s = Ub[c] + Wb[c];
#pragma unroll 4
    for (int k = 0; k < C_DIM; k++)
        s += mr[k] * Uw[c * C_DIM + k] + ar[k] * Ww[c * C_DIM + k];
    float g = 1.f / (1.f + __expf(-s));
    float nm = (1.f - g) * mr[c] + g * ar[c];
    g_newmem[m * C_DIM + c] = nm;
    nm_out[m * C_DIM + c] = nm;
}

// ---------------- K5: fused read phase, 256 threads, big tiles ----------------
#define NM_P 258
#define SS_P 130
__global__ __launch_bounds__(256) void k5_read(const float* __restrict__ q,
                                               float* __restrict__ out,
                                               float* __restrict__ attn) {
    extern __shared__ float sm[];
    float* nm = sm;                       // [128][258]
    float* qs = nm + 128 * NM_P;          // [64][256]
    float* ss = qs + 64 * 256;            // [64][130]

    int tid = threadIdx.x;
    int t0 = blockIdx.x * 64;

    for (int l = tid * 4; l < 128 * 256; l += 1024) {
        int m = l >> 8, k = l & 255;
        float4 v = *(const float4*)&g_newmem[l];
        nm[m * NM_P + k + 0] = v.x; nm[m * NM_P + k + 1] = v.y;
        nm[m * NM_P + k + 2] = v.z; nm[m * NM_P + k + 3] = v.w;
    }
    for (int l = tid * 4; l < 64 * 256; l += 1024)
        *(float4*)&qs[l] = *(const float4*)&q[(size_t)t0 * C_DIM + l];
    __syncthreads();

    int tx = tid & 15;          // scores: m = tx + j*16 ; add: c-pair = tx*2 + j*32
    int ty = tid >> 4;          // t = ty + i*16

    // ---- scores GEMM: 4t x 8m, k-packed ----
    {
        ull acc2[4][8];
#pragma unroll
        for (int i = 0; i < 4; i++)
#pragma unroll
            for (int j = 0; j < 8; j++) acc2[i][j] = 0ull;

        for (int k = 0; k < C_DIM; k += 2) {
            ull pa[4], pb[8];
#pragma unroll
            for (int i = 0; i < 4; i++)
                pa[i] = *(const ull*)&qs[(ty + i * 16) * 256 + k];
#pragma unroll
            for (int j = 0; j < 8; j++)
                pb[j] = *(const ull*)&nm[(tx + j * 16) * NM_P + k];
#pragma unroll
            for (int i = 0; i < 4; i++)
#pragma unroll
                for (int j = 0; j < 8; j++) FMA2(acc2[i][j], pa[i], pb[j]);
        }
#pragma unroll
        for (int i = 0; i < 4; i++)
#pragma unroll
            for (int j = 0; j < 8; j++) {
                float lo, hi;
                upk2(lo, hi, acc2[i][j]);
                ss[(ty + i * 16) * SS_P + tx + j * 16] = lo + hi;
            }
    }
    __syncthreads();

    // ---- softmax + hardshrink + l1-normalize per token (8 warps x 8 rows) ----
    int warp = tid >> 5, lane = tid & 31;
    for (int r = 0; r < 8; r++) {
        int t = warp * 8 + r;
        float v[4];
#pragma unroll
        for (int k = 0; k < 4; k++) v[k] = ss[t * SS_P + lane + k * 32];
        float mx = fmaxf(fmaxf(v[0], v[1]), fmaxf(v[2], v[3]));
#pragma unroll
        for (int o = 16; o > 0; o >>= 1)
            mx = fmaxf(mx, __shfl_xor_sync(0xffffffffu, mx, o));
        float e[4], sum = 0.f;
#pragma unroll
        for (int k = 0; k < 4; k++) { e[k] = __expf(v[k] - mx); sum += e[k]; }
#pragma unroll
        for (int o = 16; o > 0; o >>= 1)
            sum += __shfl_xor_sync(0xffffffffu, sum, o);
        float invs = 1.f / sum;
        float h[4], l1 = 0.f;
#pragma unroll
        for (int k = 0; k < 4; k++) {
            float a = e[k] * invs;
            float d = a - SHRINKV;
            h[k] = (d > 0.f) ? d * a / (d + EPSV) : 0.f;
            l1 += h[k];
        }
#pragma unroll
        for (int o = 16; o > 0; o >>= 1)
            l1 += __shfl_xor_sync(0xffffffffu, l1, o);
        float invl = 1.f / fmaxf(l1, EPSV);
#pragma unroll
        for (int k = 0; k < 4; k++) {
            h[k] *= invl;
            ss[t * SS_P + lane + k * 32] = h[k];
            attn[(size_t)(t0 + t) * M_DIM + lane + k * 32] = h[k];
        }
    }
    __syncthreads();

    // ---- add_memory GEMM: 4t x 16c, c-packed ----
    {
        ull acc2[4][8];
#pragma unroll
        for (int i = 0; i < 4; i++)
#pragma unroll
            for (int j = 0; j < 8; j++) acc2[i][j] = 0ull;

        for (int m = 0; m < M_DIM; m++) {
            ull pa[4], pb[8];
#pragma unroll
            for (int i = 0; i < 4; i++) {
                float a = ss[(ty + i * 16) * SS_P + m];
                pa[i] = pk2(a, a);
            }
#pragma unroll
            for (int j = 0; j < 8; j++)
                pb[j] = *(const ull*)&nm[m * NM_P + tx * 2 + j * 32];
#pragma unroll
            for (int i = 0; i < 4; i++)
#pragma unroll
                for (int j = 0; j < 8; j++) FMA2(acc2[i][j], pa[i], pb[j]);
        }
#pragma unroll
        for (int i = 0; i < 4; i++) {
            int t = t0 + ty + i * 16;
#pragma unroll
            for (int j = 0; j < 8; j++)
                *(ull*)&out[(size_t)t * 512 + 256 + tx * 2 + j * 32] = acc2[i][j];
        }
    }
    // copy q into first 256 cols
    for (int l = tid * 4; l < 64 * 256; l += 1024) {
        int t = l >> 8, c = l & 255;
        float4 v = *(const float4*)&qs[l];
        *(float4*)&out[(size_t)(t0 + t) * 512 + c] = v;
    }
}

// ---------------- launcher ----------------
extern "C" void kernel_launch(void* const* d_in, const int* in_sizes, int n_in,
                              void* d_out, int out_size) {
    const float* query = (const float*)d_in[0];
    const float* mem   = (const float*)d_in[1];
    const float* Uw    = (const float*)d_in[2];
    const float* Ub    = (const float*)d_in[3];
    const float* Ww    = (const float*)d_in[4];
    const float* Wb    = (const float*)d_in[5];

    float* out  = (float*)d_out;
    float* attn = out + (size_t)T_TOT * 512;
    float* nmo  = attn + (size_t)T_TOT * M_DIM;

    const int SMEM5 = (128 * NM_P + 64 * 256 + 64 * SS_P) * 4;  // 230,912 B
    cudaFuncSetAttribute(k5_read, cudaFuncAttributeMaxDynamicSharedMemorySize, SMEM5);

    k0_init<<<128, 256>>>();
    k1_scores<<<T_TOT / 128, 256>>>(query, mem);
    k2_scan<<<dim3(4, 128), 256>>>();
    k3_scatter<<<64, 256>>>(query);
    k4_gate<<<128, 256>>>(mem, Uw, Ub, Ww, Wb, nmo);
    k5_read<<<T_TOT / 64, 256, SMEM5>>>(query, out, attn);
}

// round 8
// speedup vs baseline: 1.4796x; 1.0058x over previous
#include <cuda_runtime.h>
#include <cstdint>
#include <math.h>

#define T_TOT 65536
#define C_DIM 256
#define M_DIM 128
#define SHRINKV 0.0025f
#define EPSV 1e-12f
#define LIST_CAP 4194304

typedef unsigned long long ull;

__device__ __forceinline__ ull pk2(float lo, float hi) {
    ull r; asm("mov.b64 %0, {%1, %2};" : "=l"(r) : "f"(lo), "f"(hi)); return r;
}
__device__ __forceinline__ void upk2(float& lo, float& hi, ull v) {
    asm("mov.b64 {%0, %1}, %2;" : "=f"(lo), "=f"(hi) : "l"(v));
}
#define FMA2(acc, a, b) asm("fma.rn.f32x2 %0, %1, %2, %0;" : "+l"(acc) : "l"(a), "l"(b))

__device__ __forceinline__ uint32_t smem_u32(const void* p) {
    uint32_t a;
    asm("{ .reg .u64 t; cvta.to.shared.u64 t, %1; cvt.u32.u64 %0, t; }" : "=r"(a) : "l"(p));
    return a;
}
#define CP_ASYNC8(dst, src) \
    asm volatile("cp.async.ca.shared.global [%0], [%1], 8;" :: "r"(dst), "l"(src))
#define CP_COMMIT() asm volatile("cp.async.commit_group;" ::: "memory")
#define CP_WAIT1()  asm volatile("cp.async.wait_group 1;" ::: "memory")
#define CP_WAIT0()  asm volatile("cp.async.wait_group 0;" ::: "memory")

// ---------------- scratch ----------------
__device__ float g_S[(size_t)M_DIM * T_TOT];   // exp(scores), [m][t]
__device__ float g_rowsum[M_DIM];
__device__ float g_l1[M_DIM];
__device__ float g_addmem[M_DIM * C_DIM];
__device__ float g_newmem[M_DIM * C_DIM];
__device__ unsigned int g_cnt;
__device__ unsigned int g_key[LIST_CAP];
__device__ float g_val[LIST_CAP];

// ---------------- K0 ----------------
__global__ void k0_init() {
    int i = blockIdx.x * blockDim.x + threadIdx.x;
    if (i < M_DIM) { g_rowsum[i] = 0.f; g_l1[i] = 0.f; }
    if (i < M_DIM * C_DIM) g_addmem[i] = 0.f;
    if (i == 0) g_cnt = 0u;
}

// ---------------- K1: S[m][t] = exp(mem[m].q[t]); rowsum ----------------
// 128t x 128m tile, 256 threads, 8x8 per thread, cp.async double-buffered (32-k chunks)
#define K1_STR 34
#define K1_BUF (128 * K1_STR)
__global__ __launch_bounds__(256) void k1_scores(const float* __restrict__ q,
                                                 const float* __restrict__ mem) {
    __shared__ float Am[2][K1_BUF];
    __shared__ float Bt[2][K1_BUF];
    __shared__ float rsum[128];

    int tid = threadIdx.x;
    int tx = tid & 15;        // t = tx + j*16
    int ty = tid >> 4;        // m = ty + i*16
    int t0 = blockIdx.x * 128;

    int lr = tid >> 1;            // 0..127 row
    int kb = (tid & 1) * 16;      // 0 or 16 (within 32-k chunk)

    uint32_t sA = smem_u32(&Am[0][0]);
    uint32_t sB = smem_u32(&Bt[0][0]);

    ull acc2[8][8];
#pragma unroll
    for (int i = 0; i < 8; i++)
#pragma unroll
        for (int j = 0; j < 8; j++) acc2[i][j] = 0ull;

    const float* msrc_b = mem + lr * C_DIM + kb;
    const float* qsrc_b = q + (size_t)(t0 + lr) * C_DIM + kb;
    uint32_t adst = sA + (uint32_t)(lr * K1_STR + kb) * 4;
    uint32_t bdst = sB + (uint32_t)(lr * K1_STR + kb) * 4;

    // prologue: issue chunk 0 into buf 0
    {
        const float* ms = msrc_b;
        const float* qs_ = qsrc_b;
#pragma unroll
        for (int u = 0; u < 8; u++) {
            CP_ASYNC8(adst + u * 8, ms + u * 2);
            CP_ASYNC8(bdst + u * 8, qs_ + u * 2);
        }
        CP_COMMIT();
    }

    for (int c = 0; c < 8; c++) {
        int buf = c & 1;
        if (c < 7) {
            int nb = (c + 1) & 1;
            const float* ms = msrc_b + (c + 1) * 32;
            const float* qs_ = qsrc_b + (c + 1) * 32;
            uint32_t ad = adst + (uint32_t)nb * K1_BUF * 4;
            uint32_t bd = bdst + (uint32_t)nb * K1_BUF * 4;
#pragma unroll
            for (int u = 0; u < 8; u++) {
                CP_ASYNC8(ad + u * 8, ms + u * 2);
                CP_ASYNC8(bd + u * 8, qs_ + u * 2);
            }
            CP_COMMIT();
            CP_WAIT1();
        } else {
            CP_WAIT0();
        }
        __syncthreads();

        const float* A = &Am[buf][0];
        const float* B = &Bt[buf][0];
#pragma unroll
        for (int k = 0; k < 32; k += 2) {
            ull pa[8], pb[8];
#pragma unroll
            for (int i = 0; i < 8; i++)
                pa[i] = *(const ull*)&A[(ty + i * 16) * K1_STR + k];
#pragma unroll
            for (int j = 0; j < 8; j++)
                pb[j] = *(const ull*)&B[(tx + j * 16) * K1_STR + k];
#pragma unroll
            for (int i = 0; i < 8; i++)
#pragma unroll
                for (int j = 0; j < 8; j++) FMA2(acc2[i][j], pa[i], pb[j]);
        }
        __syncthreads();
    }

    if (tid < 128) rsum[tid] = 0.f;
    __syncthreads();

#pragma unroll
    for (int i = 0; i < 8; i++) {
        int m = ty + i * 16;
        float part = 0.f;
#pragma unroll
        for (int j = 0; j < 8; j++) {
            float lo, hi;
            upk2(lo, hi, acc2[i][j]);
            float e = __expf(lo + hi);
            part += e;
            g_S[(size_t)m * T_TOT + t0 + tx + j * 16] = e;
        }
        atomicAdd(&rsum[m], part);
    }
    __syncthreads();
    if (tid < 128) atomicAdd(&g_rowsum[tid], rsum[tid]);
}

// ---------------- K2: scan survivors + shrink + l1 (fused) ----------------
__global__ __launch_bounds__(256) void k2_scan() {
    int m = blockIdx.y;
    float rs = g_rowsum[m];
    float thr = SHRINKV * rs;
    float inv = 1.0f / rs;
    size_t rowbase = (size_t)m * T_TOT;
    int tbase = blockIdx.x * 16384 + threadIdx.x * 4;
#pragma unroll
    for (int j = 0; j < 16; j++) {
        int t = tbase + j * 1024;
        float4 v = *(const float4*)&g_S[rowbase + t];
        float e[4] = {v.x, v.y, v.z, v.w};
#pragma unroll
        for (int k = 0; k < 4; k++) {
            if (e[k] > thr) {
                float a = e[k] * inv;
                float d = a - SHRINKV;
                float h = (d > 0.f) ? d * a / (d + EPSV) : 0.f;
                unsigned int pos = atomicAdd(&g_cnt, 1u);
                if (pos < LIST_CAP) {
                    g_key[pos] = ((unsigned int)(t + k) << 7) | (unsigned int)m;
                    g_val[pos] = h;
                }
                atomicAdd(&g_l1[m], h);
            }
        }
    }
}

// ---------------- K3: add_mem[m][c] += h * q[t][c] ----------------
__global__ __launch_bounds__(256) void k3_scatter(const float* __restrict__ q) {
    unsigned int n = g_cnt; if (n > LIST_CAP) n = LIST_CAP;
    int c = threadIdx.x;
    for (unsigned int i = blockIdx.x; i < n; i += gridDim.x) {
        unsigned int key = g_key[i];
        unsigned int t = key >> 7, m = key & 127;
        float h = g_val[i];
        atomicAdd(&g_addmem[m * C_DIM + c], h * q[(size_t)t * C_DIM + c]);
    }
}

// ---------------- K4: gate + new_mem (16 blocks x 8 m, weight reuse) ----------------
__global__ __launch_bounds__(256) void k4_gate(const float* __restrict__ mem,
                                               const float* __restrict__ Uw,
                                               const float* __restrict__ Ub,
                                               const float* __restrict__ Ww,
                                               const float* __restrict__ Wb,
                                               float* __restrict__ nm_out) {
    __shared__ float mr[8][256], ar[8][256];
    int c = threadIdx.x;
    int m0 = blockIdx.x * 8;

    for (int i = 0; i < 8; i++) {
        int m = m0 + i;
        float invl1 = 1.0f / fmaxf(g_l1[m], EPSV);
        mr[i][c] = mem[m * C_DIM + c];
        ar[i][c] = g_addmem[m * C_DIM + c] * invl1;
    }
    __syncthreads();

    float s[8];
    float b = Ub[c] + Wb[c];
#pragma unroll
    for (int i = 0; i < 8; i++) s[i] = b;

    const float* uw = Uw + c * C_DIM;
    const float* ww = Ww + c * C_DIM;
#pragma unroll 4
    for (int k = 0; k < C_DIM; k++) {
        float wu = uw[k], wv = ww[k];
#pragma unroll
        for (int i = 0; i < 8; i++)
            s[i] += mr[i][k] * wu + ar[i][k] * wv;
    }
#pragma unroll
    for (int i = 0; i < 8; i++) {
        int m = m0 + i;
        float g = 1.f / (1.f + __expf(-s[i]));
        float nm = (1.f - g) * mr[i][c] + g * ar[i][c];
        g_newmem[m * C_DIM + c] = nm;
        nm_out[m * C_DIM + c] = nm;
    }
}

// ---------------- K5: fused read phase, 256 threads, big tiles ----------------
#define NM_P 258
#define SS_P 130
__global__ __launch_bounds__(256) void k5_read(const float* __restrict__ q,
                                               float* __restrict__ out,
                                               float* __restrict__ attn) {
    extern __shared__ float sm[];
    float* nm = sm;                       // [128][258]
    float* qs = nm + 128 * NM_P;          // [64][256]
    float* ss = qs + 64 * 256;            // [64][130]

    int tid = threadIdx.x;
    int t0 = blockIdx.x * 64;

    for (int l = tid * 4; l < 128 * 256; l += 1024) {
        int m = l >> 8, k = l & 255;
        float4 v = *(const float4*)&g_newmem[l];
        nm[m * NM_P + k + 0] = v.x; nm[m * NM_P + k + 1] = v.y;
        nm[m * NM_P + k + 2] = v.z; nm[m * NM_P + k + 3] = v.w;
    }
    // q: global -> reg -> qs AND out (first 256 cols), fused
    for (int l = tid * 4; l < 64 * 256; l += 1024) {
        int t = l >> 8, c = l & 255;
        float4 v = *(const float4*)&q[(size_t)t0 * C_DIM + l];
        *(float4*)&qs[l] = v;
        *(float4*)&out[(size_t)(t0 + t) * 512 + c] = v;
    }
    __syncthreads();

    int tx = tid & 15;          // scores: m = tx + j*16 ; add: c-pair = tx*2 + j*32
    int ty = tid >> 4;          // t = ty + i*16

    // ---- scores GEMM: 4t x 8m, k-packed, unroll 2 ----
    {
        ull acc2[4][8];
#pragma unroll
        for (int i = 0; i < 4; i++)
#pragma unroll
            for (int j = 0; j < 8; j++) acc2[i][j] = 0ull;

#pragma unroll 2
        for (int k = 0; k < C_DIM; k += 2) {
            ull pa[4], pb[8];
#pragma unroll
            for (int i = 0; i < 4; i++)
                pa[i] = *(const ull*)&qs[(ty + i * 16) * 256 + k];
#pragma unroll
            for (int j = 0; j < 8; j++)
                pb[j] = *(const ull*)&nm[(tx + j * 16) * NM_P + k];
#pragma unroll
            for (int i = 0; i < 4; i++)
#pragma unroll
                for (int j = 0; j < 8; j++) FMA2(acc2[i][j], pa[i], pb[j]);
        }
#pragma unroll
        for (int i = 0; i < 4; i++)
#pragma unroll
            for (int j = 0; j < 8; j++) {
                float lo, hi;
                upk2(lo, hi, acc2[i][j]);
                ss[(ty + i * 16) * SS_P + tx + j * 16] = lo + hi;
            }
    }
    __syncthreads();

    // ---- softmax + hardshrink + l1-normalize per token (8 warps x 8 rows) ----
    int warp = tid >> 5, lane = tid & 31;
    for (int r = 0; r < 8; r++) {
        int t = warp * 8 + r;
        float v[4];
#pragma unroll
        for (int k = 0; k < 4; k++) v[k] = ss[t * SS_P + lane + k * 32];
        float mx = fmaxf(fmaxf(v[0], v[1]), fmaxf(v[2], v[3]));
#pragma unroll
        for (int o = 16; o > 0; o >>= 1)
            mx = fmaxf(mx, __shfl_xor_sync(0xffffffffu, mx, o));
        float e[4], sum = 0.f;
#pragma unroll
        for (int k = 0; k < 4; k++) { e[k] = __expf(v[k] - mx); sum += e[k]; }
#pragma unroll
        for (int o = 16; o > 0; o >>= 1)
            sum += __shfl_xor_sync(0xffffffffu, sum, o);
        float invs = 1.f / sum;
        float h[4], l1 = 0.f;
#pragma unroll
        for (int k = 0; k < 4; k++) {
            float a = e[k] * invs;
            float d = a - SHRINKV;
            h[k] = (d > 0.f) ? d * a / (d + EPSV) : 0.f;
            l1 += h[k];
        }
#pragma unroll
        for (int o = 16; o > 0; o >>= 1)
            l1 += __shfl_xor_sync(0xffffffffu, l1, o);
        float invl = 1.f / fmaxf(l1, EPSV);
#pragma unroll
        for (int k = 0; k < 4; k++) {
            h[k] *= invl;
            ss[t * SS_P + lane + k * 32] = h[k];
            attn[(size_t)(t0 + t) * M_DIM + lane + k * 32] = h[k];
        }
    }
    __syncthreads();

    // ---- add_memory GEMM: 4t x 16c, c-packed, unroll 2 ----
    {
        ull acc2[4][8];
#pragma unroll
        for (int i = 0; i < 4; i++)
#pragma unroll
            for (int j = 0; j < 8; j++) acc2[i][j] = 0ull;

#pragma unroll 2
        for (int m = 0; m < M_DIM; m++) {
            ull pa[4], pb[8];
#pragma unroll
            for (int i = 0; i < 4; i++) {
                float a = ss[(ty + i * 16) * SS_P + m];
                pa[i] = pk2(a, a);
            }
#pragma unroll
            for (int j = 0; j < 8; j++)
                pb[j] = *(const ull*)&nm[m * NM_P + tx * 2 + j * 32];
#pragma unroll
            for (int i = 0; i < 4; i++)
#pragma unroll
                for (int j = 0; j < 8; j++) FMA2(acc2[i][j], pa[i], pb[j]);
        }
#pragma unroll
        for (int i = 0; i < 4; i++) {
            int t = t0 + ty + i * 16;
#pragma unroll
            for (int j = 0; j < 8; j++)
                *(ull*)&out[(size_t)t * 512 + 256 + tx * 2 + j * 32] = acc2[i][j];
        }
    }
}

// ---------------- launcher ----------------
extern "C" void kernel_launch(void* const* d_in, const int* in_sizes, int n_in,
                              void* d_out, int out_size) {
    const float* query = (const float*)d_in[0];
    const float* mem   = (const float*)d_in[1];
    const float* Uw    = (const float*)d_in[2];
    const float* Ub    = (const float*)d_in[3];
    const float* Ww    = (const float*)d_in[4];
    const float* Wb    = (const float*)d_in[5];

    float* out  = (float*)d_out;
    float* attn = out + (size_t)T_TOT * 512;
    float* nmo  = attn + (size_t)T_TOT * M_DIM;

    const int SMEM5 = (128 * NM_P + 64 * 256 + 64 * SS_P) * 4;  // 230,912 B
    cudaFuncSetAttribute(k5_read, cudaFuncAttributeMaxDynamicSharedMemorySize, SMEM5);

    k0_init<<<128, 256>>>();
    k1_scores<<<T_TOT / 128, 256>>>(query, mem);
    k2_scan<<<dim3(4, 128), 256>>>();
    k3_scatter<<<64, 256>>>(query);
    k4_gate<<<16, 256>>>(mem, Uw, Ub, Ww, Wb, nmo);
    k5_read<<<T_TOT / 64, 256, SMEM5>>>(query, out, attn);
}

// round 9
// speedup vs baseline: 1.6654x; 1.1256x over previous
#include <cuda_runtime.h>
#include <cuda_bf16.h>
#include <cstdint>
#include <math.h>

#define T_TOT 65536
#define C_DIM 256
#define M_DIM 128
#define SHRINKV 0.0025f
#define EPSV 1e-12f
#define LIST_CAP 4194304

typedef unsigned long long ull;

__device__ __forceinline__ ull pk2(float lo, float hi) {
    ull r; asm("mov.b64 %0, {%1, %2};" : "=l"(r) : "f"(lo), "f"(hi)); return r;
}
__device__ __forceinline__ void upk2(float& lo, float& hi, ull v) {
    asm("mov.b64 {%0, %1}, %2;" : "=f"(lo), "=f"(hi) : "l"(v));
}
#define FMA2(acc, a, b) asm("fma.rn.f32x2 %0, %1, %2, %0;" : "+l"(acc) : "l"(a), "l"(b))

__device__ __forceinline__ uint32_t smem_u32(const void* p) {
    uint32_t a;
    asm("{ .reg .u64 t; cvta.to.shared.u64 t, %1; cvt.u32.u64 %0, t; }" : "=r"(a) : "l"(p));
    return a;
}
#define LDMATRIX_X4(r0, r1, r2, r3, addr) \
    asm volatile("ldmatrix.sync.aligned.m8n8.x4.shared.b16 {%0,%1,%2,%3}, [%4];" \
        : "=r"(r0), "=r"(r1), "=r"(r2), "=r"(r3) : "r"(addr))
#define MMA_BF16(acc, a, b) \
    asm volatile("mma.sync.aligned.m16n8k16.row.col.f32.bf16.bf16.f32 " \
        "{%0,%1,%2,%3}, {%4,%5,%6,%7}, {%8,%9}, {%0,%1,%2,%3};" \
        : "+f"((acc)[0]), "+f"((acc)[1]), "+f"((acc)[2]), "+f"((acc)[3]) \
        : "r"((a)[0]), "r"((a)[1]), "r"((a)[2]), "r"((a)[3]), "r"((b)[0]), "r"((b)[1]))

// ---------------- scratch ----------------
__device__ float g_S[(size_t)M_DIM * T_TOT];   // exp(scores), [m][t]
__device__ float g_rowsum[M_DIM];
__device__ float g_l1[M_DIM];
__device__ float g_addmem[M_DIM * C_DIM];
__device__ float g_newmem[M_DIM * C_DIM];
__device__ unsigned int g_cnt;
__device__ unsigned int g_key[LIST_CAP];
__device__ float g_val[LIST_CAP];
__device__ __nv_bfloat16 g_mh[M_DIM * C_DIM];  // mem hi (bf16)
__device__ __nv_bfloat16 g_ml[M_DIM * C_DIM];  // mem lo (bf16 residual)

// ---------------- K0: zero accumulators + mem bf16 split ----------------
__global__ void k0_init(const float* __restrict__ mem) {
    int i = blockIdx.x * blockDim.x + threadIdx.x;   // 0..32767
    if (i < M_DIM) { g_rowsum[i] = 0.f; g_l1[i] = 0.f; }
    if (i == 0) g_cnt = 0u;
    float v = mem[i];
    __nv_bfloat16 h = __float2bfloat16(v);
    g_mh[i] = h;
    g_ml[i] = __float2bfloat16(v - __bfloat162float(h));
    if (i < M_DIM * C_DIM) g_addmem[i] = 0.f;
}

// ---------------- K1: S[m][t] = exp(mem[m].q[t]) via mma.sync bf16 3-pass ----------------
// block: 128m x 128t, 256 threads (8 warps, 4m x 2t grid of 32m x 64t warp tiles)
#define QB_STR 264   // bf16 per smem row (256 + 8 pad), 528 B = 33*16B
__global__ __launch_bounds__(256) void k1_mma(const float* __restrict__ q) {
    extern __shared__ __nv_bfloat16 qsm[];
    __nv_bfloat16* Bh = qsm;                 // [128][264]
    __nv_bfloat16* Bl = qsm + 128 * QB_STR;  // [128][264]
    __shared__ float rsum[128];

    int tid = threadIdx.x, lane = tid & 31, warp = tid >> 5;
    int t0 = blockIdx.x * 128;
    int m0 = (warp >> 1) * 32;     // 0,32,64,96
    int t0w = (warp & 1) * 64;     // 0 or 64

    // ---- stage q tile -> bf16 hi/lo smem ----
    for (int i = tid * 4; i < 128 * 256; i += 1024) {
        int t = i >> 8, k = i & 255;
        float4 v = *(const float4*)&q[(size_t)(t0 + t) * C_DIM + k];
        float vv[4] = {v.x, v.y, v.z, v.w};
#pragma unroll
        for (int u = 0; u < 4; u++) {
            __nv_bfloat16 h = __float2bfloat16(vv[u]);
            Bh[t * QB_STR + k + u] = h;
            Bl[t * QB_STR + k + u] = __float2bfloat16(vv[u] - __bfloat162float(h));
        }
    }
    if (tid < 128) rsum[tid] = 0.f;
    __syncthreads();

    uint32_t sBh = smem_u32(Bh), sBl = smem_u32(Bl);

    float acc[2][8][4];
#pragma unroll
    for (int mf = 0; mf < 2; mf++)
#pragma unroll
        for (int nf = 0; nf < 8; nf++)
#pragma unroll
            for (int u = 0; u < 4; u++) acc[mf][nf][u] = 0.f;

    int g = lane >> 2, t2 = (lane & 3) * 2;
    // ldmatrix per-lane address pattern (within a 16t x 16k piece pair)
    int lrow = (lane & 7) + ((lane >> 4) << 3);   // +8 rows for halves 2,3
    int lcol = (lane & 8);                         // +8 k for halves 1,3

    for (int ks = 0; ks < 16; ks++) {
        int k0 = ks * 16;
        // ---- a-frags: LDG from precomputed bf16 mem (L1-resident) ----
        uint32_t ah[2][4], al[2][4];
#pragma unroll
        for (int mf = 0; mf < 2; mf++) {
            int mb = m0 + mf * 16;
            ah[mf][0] = *(const uint32_t*)&g_mh[(mb + g) * C_DIM + k0 + t2];
            ah[mf][1] = *(const uint32_t*)&g_mh[(mb + g + 8) * C_DIM + k0 + t2];
            ah[mf][2] = *(const uint32_t*)&g_mh[(mb + g) * C_DIM + k0 + t2 + 8];
            ah[mf][3] = *(const uint32_t*)&g_mh[(mb + g + 8) * C_DIM + k0 + t2 + 8];
            al[mf][0] = *(const uint32_t*)&g_ml[(mb + g) * C_DIM + k0 + t2];
            al[mf][1] = *(const uint32_t*)&g_ml[(mb + g + 8) * C_DIM + k0 + t2];
            al[mf][2] = *(const uint32_t*)&g_ml[(mb + g) * C_DIM + k0 + t2 + 8];
            al[mf][3] = *(const uint32_t*)&g_ml[(mb + g + 8) * C_DIM + k0 + t2 + 8];
        }
        // ---- b-frags: ldmatrix x4 (two 8-t n-frags per call) ----
        uint32_t bh[8][2], bl[8][2];
#pragma unroll
        for (int pr = 0; pr < 4; pr++) {
            int tb = t0w + pr * 16;
            uint32_t off = (uint32_t)((tb + lrow) * QB_STR + k0 + lcol) * 2;
            LDMATRIX_X4(bh[pr * 2][0], bh[pr * 2][1], bh[pr * 2 + 1][0], bh[pr * 2 + 1][1], sBh + off);
            LDMATRIX_X4(bl[pr * 2][0], bl[pr * 2][1], bl[pr * 2 + 1][0], bl[pr * 2 + 1][1], sBl + off);
        }
        // ---- 3-pass accumulate ----
#pragma unroll
        for (int mf = 0; mf < 2; mf++)
#pragma unroll
            for (int nf = 0; nf < 8; nf++) {
                MMA_BF16(acc[mf][nf], ah[mf], bh[nf]);
                MMA_BF16(acc[mf][nf], ah[mf], bl[nf]);
                MMA_BF16(acc[mf][nf], al[mf], bh[nf]);
            }
    }

    // ---- epilogue: exp, store [m][t], rowsum ----
#pragma unroll
    for (int mf = 0; mf < 2; mf++) {
        float p0 = 0.f, p1 = 0.f;
        int mr0 = m0 + mf * 16 + g;
        int mr1 = mr0 + 8;
#pragma unroll
        for (int nf = 0; nf < 8; nf++) {
            int ta = t0 + t0w + nf * 8 + t2;
            float e0 = __expf(acc[mf][nf][0]);
            float e1 = __expf(acc[mf][nf][1]);
            float e2 = __expf(acc[mf][nf][2]);
            float e3 = __expf(acc[mf][nf][3]);
            *(float2*)&g_S[(size_t)mr0 * T_TOT + ta] = make_float2(e0, e1);
            *(float2*)&g_S[(size_t)mr1 * T_TOT + ta] = make_float2(e2, e3);
            p0 += e0 + e1;
            p1 += e2 + e3;
        }
#pragma unroll
        for (int o = 1; o < 4; o <<= 1) {
            p0 += __shfl_xor_sync(0xffffffffu, p0, o);
            p1 += __shfl_xor_sync(0xffffffffu, p1, o);
        }
        if ((lane & 3) == 0) {
            atomicAdd(&rsum[mr0], p0);
            atomicAdd(&rsum[mr1], p1);
        }
    }
    __syncthreads();
    if (tid < 128) atomicAdd(&g_rowsum[tid], rsum[tid]);
}

// ---------------- K2: scan survivors + shrink + l1 (fused) ----------------
__global__ __launch_bounds__(256) void k2_scan() {
    int m = blockIdx.y;
    float rs = g_rowsum[m];
    float thr = SHRINKV * rs;
    float inv = 1.0f / rs;
    size_t rowbase = (size_t)m * T_TOT;
    int tbase = blockIdx.x * 16384 + threadIdx.x * 4;
#pragma unroll
    for (int j = 0; j < 16; j++) {
        int t = tbase + j * 1024;
        float4 v = *(const float4*)&g_S[rowbase + t];
        float e[4] = {v.x, v.y, v.z, v.w};
#pragma unroll
        for (int k = 0; k < 4; k++) {
            if (e[k] > thr) {
                float a = e[k] * inv;
                float d = a - SHRINKV;
                float h = (d > 0.f) ? d * a / (d + EPSV) : 0.f;
                unsigned int pos = atomicAdd(&g_cnt, 1u);
                if (pos < LIST_CAP) {
                    g_key[pos] = ((unsigned int)(t + k) << 7) | (unsigned int)m;
                    g_val[pos] = h;
                }
                atomicAdd(&g_l1[m], h);
            }
        }
    }
}

// ---------------- K3: add_mem[m][c] += h * q[t][c] ----------------
__global__ __launch_bounds__(256) void k3_scatter(const float* __restrict__ q) {
    unsigned int n = g_cnt; if (n > LIST_CAP) n = LIST_CAP;
    int c = threadIdx.x;
    for (unsigned int i = blockIdx.x; i < n; i += gridDim.x) {
        unsigned int key = g_key[i];
        unsigned int t = key >> 7, m = key & 127;
        float h = g_val[i];
        atomicAdd(&g_addmem[m * C_DIM + c], h * q[(size_t)t * C_DIM + c]);
    }
}

// ---------------- K4: gate + new_mem (16 blocks x 8 m, weight reuse) ----------------
__global__ __launch_bounds__(256) void k4_gate(const float* __restrict__ mem,
                                               const float* __restrict__ Uw,
                                               const float* __restrict__ Ub,
                                               const float* __restrict__ Ww,
                                               const float* __restrict__ Wb,
                                               float* __restrict__ nm_out) {
    __shared__ float mr[8][256], ar[8][256];
    int c = threadIdx.x;
    int m0 = blockIdx.x * 8;

    for (int i = 0; i < 8; i++) {
        int m = m0 + i;
        float invl1 = 1.0f / fmaxf(g_l1[m], EPSV);
        mr[i][c] = mem[m * C_DIM + c];
        ar[i][c] = g_addmem[m * C_DIM + c] * invl1;
    }
    __syncthreads();

    float s[8];
    float b = Ub[c] + Wb[c];
#pragma unroll
    for (int i = 0; i < 8; i++) s[i] = b;

    const float* uw = Uw + c * C_DIM;
    const float* ww = Ww + c * C_DIM;
#pragma unroll 4
    for (int k = 0; k < C_DIM; k++) {
        float wu = uw[k], wv = ww[k];
#pragma unroll
        for (int i = 0; i < 8; i++)
            s[i] += mr[i][k] * wu + ar[i][k] * wv;
    }
#pragma unroll
    for (int i = 0; i < 8; i++) {
        int m = m0 + i;
        float g = 1.f / (1.f + __expf(-s[i]));
        float nm = (1.f - g) * mr[i][c] + g * ar[i][c];
        g_newmem[m * C_DIM + c] = nm;
        nm_out[m * C_DIM + c] = nm;
    }
}

// ---------------- K5: fused read phase (unchanged, passing at 563us) ----------------
#define NM_P 258
#define SS_P 130
__global__ __launch_bounds__(256) void k5_read(const float* __restrict__ q,
                                               float* __restrict__ out,
                                               float* __restrict__ attn) {
    extern __shared__ float sm[];
    float* nm = sm;                       // [128][258]
    float* qs = nm + 128 * NM_P;          // [64][256]
    float* ss = qs + 64 * 256;            // [64][130]

    int tid = threadIdx.x;
    int t0 = blockIdx.x * 64;

    for (int l = tid * 4; l < 128 * 256; l += 1024) {
        int m = l >> 8, k = l & 255;
        float4 v = *(const float4*)&g_newmem[l];
        nm[m * NM_P + k + 0] = v.x; nm[m * NM_P + k + 1] = v.y;
        nm[m * NM_P + k + 2] = v.z; nm[m * NM_P + k + 3] = v.w;
    }
    for (int l = tid * 4; l < 64 * 256; l += 1024) {
        int t = l >> 8, c = l & 255;
        float4 v = *(const float4*)&q[(size_t)t0 * C_DIM + l];
        *(float4*)&qs[l] = v;
        *(float4*)&out[(size_t)(t0 + t) * 512 + c] = v;
    }
    __syncthreads();

    int tx = tid & 15;
    int ty = tid >> 4;

    // ---- scores GEMM: 4t x 8m, k-packed ----
    {
        ull acc2[4][8];
#pragma unroll
        for (int i = 0; i < 4; i++)
#pragma unroll
            for (int j = 0; j < 8; j++) acc2[i][j] = 0ull;

#pragma unroll 2
        for (int k = 0; k < C_DIM; k += 2) {
            ull pa[4], pb[8];
#pragma unroll
            for (int i = 0; i < 4; i++)
                pa[i] = *(const ull*)&qs[(ty + i * 16) * 256 + k];
#pragma unroll
            for (int j = 0; j < 8; j++)
                pb[j] = *(const ull*)&nm[(tx + j * 16) * NM_P + k];
#pragma unroll
            for (int i = 0; i < 4; i++)
#pragma unroll
                for (int j = 0; j < 8; j++) FMA2(acc2[i][j], pa[i], pb[j]);
        }
#pragma unroll
        for (int i = 0; i < 4; i++)
#pragma unroll
            for (int j = 0; j < 8; j++) {
                float lo, hi;
                upk2(lo, hi, acc2[i][j]);
                ss[(ty + i * 16) * SS_P + tx + j * 16] = lo + hi;
            }
    }
    __syncthreads();

    int warp = tid >> 5, lane = tid & 31;
    for (int r = 0; r < 8; r++) {
        int t = warp * 8 + r;
        float v[4];
#pragma unroll
        for (int k = 0; k < 4; k++) v[k] = ss[t * SS_P + lane + k * 32];
        float mx = fmaxf(fmaxf(v[0], v[1]), fmaxf(v[2], v[3]));
#pragma unroll
        for (int o = 16; o > 0; o >>= 1)
            mx = fmaxf(mx, __shfl_xor_sync(0xffffffffu, mx, o));
        float e[4], sum = 0.f;
#pragma unroll
        for (int k = 0; k < 4; k++) { e[k] = __expf(v[k] - mx); sum += e[k]; }
#pragma unroll
        for (int o = 16; o > 0; o >>= 1)
            sum += __shfl_xor_sync(0xffffffffu, sum, o);
        float invs = 1.f / sum;
        float h[4], l1 = 0.f;
#pragma unroll
        for (int k = 0; k < 4; k++) {
            float a = e[k] * invs;
            float d = a - SHRINKV;
            h[k] = (d > 0.f) ? d * a / (d + EPSV) : 0.f;
            l1 += h[k];
        }
#pragma unroll
        for (int o = 16; o > 0; o >>= 1)
            l1 += __shfl_xor_sync(0xffffffffu, l1, o);
        float invl = 1.f / fmaxf(l1, EPSV);
#pragma unroll
        for (int k = 0; k < 4; k++) {
            h[k] *= invl;
            ss[t * SS_P + lane + k * 32] = h[k];
            attn[(size_t)(t0 + t) * M_DIM + lane + k * 32] = h[k];
        }
    }
    __syncthreads();

    // ---- add_memory GEMM: 4t x 16c, c-packed ----
    {
        ull acc2[4][8];
#pragma unroll
        for (int i = 0; i < 4; i++)
#pragma unroll
            for (int j = 0; j < 8; j++) acc2[i][j] = 0ull;

#pragma unroll 2
        for (int m = 0; m < M_DIM; m++) {
            ull pa[4], pb[8];
#pragma unroll
            for (int i = 0; i < 4; i++) {
                float a = ss[(ty + i * 16) * SS_P + m];
                pa[i] = pk2(a, a);
            }
#pragma unroll
            for (int j = 0; j < 8; j++)
                pb[j] = *(const ull*)&nm[m * NM_P + tx * 2 + j * 32];
#pragma unroll
            for (int i = 0; i < 4; i++)
#pragma unroll
                for (int j = 0; j < 8; j++) FMA2(acc2[i][j], pa[i], pb[j]);
        }
#pragma unroll
        for (int i = 0; i < 4; i++) {
            int t = t0 + ty + i * 16;
#pragma unroll
            for (int j = 0; j < 8; j++)
                *(ull*)&out[(size_t)t * 512 + 256 + tx * 2 + j * 32] = acc2[i][j];
        }
    }
}

// ---------------- launcher ----------------
extern "C" void kernel_launch(void* const* d_in, const int* in_sizes, int n_in,
                              void* d_out, int out_size) {
    const float* query = (const float*)d_in[0];
    const float* mem   = (const float*)d_in[1];
    const float* Uw    = (const float*)d_in[2];
    const float* Ub    = (const float*)d_in[3];
    const float* Ww    = (const float*)d_in[4];
    const float* Wb    = (const float*)d_in[5];

    float* out  = (float*)d_out;
    float* attn = out + (size_t)T_TOT * 512;
    float* nmo  = attn + (size_t)T_TOT * M_DIM;

    const int SMEM1 = 2 * 128 * QB_STR * 2;   // 135,168 B
    const int SMEM5 = (128 * NM_P + 64 * 256 + 64 * SS_P) * 4;
    cudaFuncSetAttribute(k1_mma, cudaFuncAttributeMaxDynamicSharedMemorySize, SMEM1);
    cudaFuncSetAttribute(k5_read, cudaFuncAttributeMaxDynamicSharedMemorySize, SMEM5);

    k0_init<<<128, 256>>>(mem);
    k1_mma<<<T_TOT / 128, 256, SMEM1>>>(query);
    k2_scan<<<dim3(4, 128), 256>>>();
    k3_scatter<<<64, 256>>>(query);
    k4_gate<<<16, 256>>>(mem, Uw, Ub, Ww, Wb, nmo);
    k5_read<<<T_TOT / 64, 256, SMEM5>>>(query, out, attn);
}

// round 10
// speedup vs baseline: 1.8936x; 1.1370x over previous
#include <cuda_runtime.h>
#include <cuda_bf16.h>
#include <cstdint>
#include <math.h>

#define T_TOT 65536
#define C_DIM 256
#define M_DIM 128
#define SHRINKV 0.0025f
#define EPSV 1e-12f
#define LIST_CAP 4194304

typedef unsigned long long ull;

__device__ __forceinline__ uint32_t smem_u32(const void* p) {
    uint32_t a;
    asm("{ .reg .u64 t; cvta.to.shared.u64 t, %1; cvt.u32.u64 %0, t; }" : "=r"(a) : "l"(p));
    return a;
}
#define LDMATRIX_X4(r0, r1, r2, r3, addr) \
    asm volatile("ldmatrix.sync.aligned.m8n8.x4.shared.b16 {%0,%1,%2,%3}, [%4];" \
        : "=r"(r0), "=r"(r1), "=r"(r2), "=r"(r3) : "r"(addr))
#define LDMATRIX_X4T(r0, r1, r2, r3, addr) \
    asm volatile("ldmatrix.sync.aligned.m8n8.x4.trans.shared.b16 {%0,%1,%2,%3}, [%4];" \
        : "=r"(r0), "=r"(r1), "=r"(r2), "=r"(r3) : "r"(addr))
#define MMA_BF16(acc, a, b) \
    asm volatile("mma.sync.aligned.m16n8k16.row.col.f32.bf16.bf16.f32 " \
        "{%0,%1,%2,%3}, {%4,%5,%6,%7}, {%8,%9}, {%0,%1,%2,%3};" \
        : "+f"((acc)[0]), "+f"((acc)[1]), "+f"((acc)[2]), "+f"((acc)[3]) \
        : "r"((a)[0]), "r"((a)[1]), "r"((a)[2]), "r"((a)[3]), "r"((b)[0]), "r"((b)[1]))

// pack two floats -> bf16x2 (x = low)
__device__ __forceinline__ uint32_t bfpair(float x, float y) {
    __nv_bfloat162 p = __floats2bfloat162_rn(x, y);
    return *(uint32_t*)&p;
}
__device__ __forceinline__ float bf_lo_f(uint32_t p) {
    return __uint_as_float((p & 0xFFFFu) << 16);
}
__device__ __forceinline__ float bf_hi_f(uint32_t p) {
    return __uint_as_float(p & 0xFFFF0000u);
}
// build hi pair + residual-lo pair from two floats
__device__ __forceinline__ void split2(float x, float y, uint32_t& hi, uint32_t& lo) {
    hi = bfpair(x, y);
    lo = bfpair(x - bf_lo_f(hi), y - bf_hi_f(hi));
}

// ---------------- scratch ----------------
__device__ float g_S[(size_t)M_DIM * T_TOT];   // exp(scores), [m][t]
__device__ float g_rowsum[M_DIM];
__device__ float g_l1[M_DIM];
__device__ float g_addmem[M_DIM * C_DIM];
__device__ float g_newmem[M_DIM * C_DIM];
__device__ unsigned int g_cnt;
__device__ unsigned int g_key[LIST_CAP];
__device__ float g_val[LIST_CAP];
__device__ __nv_bfloat16 g_mh[M_DIM * C_DIM];
__device__ __nv_bfloat16 g_ml[M_DIM * C_DIM];

// ---------------- K0 ----------------
__global__ void k0_init(const float* __restrict__ mem) {
    int i = blockIdx.x * blockDim.x + threadIdx.x;
    if (i < M_DIM) { g_rowsum[i] = 0.f; g_l1[i] = 0.f; }
    if (i == 0) g_cnt = 0u;
    float v = mem[i];
    __nv_bfloat16 h = __float2bfloat16(v);
    g_mh[i] = h;
    g_ml[i] = __float2bfloat16(v - __bfloat162float(h));
    if (i < M_DIM * C_DIM) g_addmem[i] = 0.f;
}

// ---------------- K1: S[m][t] = exp(mem[m].q[t]) via mma.sync (unchanged, proven) ----------------
#define QB_STR 264
__global__ __launch_bounds__(256) void k1_mma(const float* __restrict__ q) {
    extern __shared__ __nv_bfloat16 qsm[];
    __nv_bfloat16* Bh = qsm;
    __nv_bfloat16* Bl = qsm + 128 * QB_STR;
    __shared__ float rsum[128];

    int tid = threadIdx.x, lane = tid & 31, warp = tid >> 5;
    int t0 = blockIdx.x * 128;
    int m0 = (warp >> 1) * 32;
    int t0w = (warp & 1) * 64;

    for (int i = tid * 4; i < 128 * 256; i += 1024) {
        int t = i >> 8, k = i & 255;
        float4 v = *(const float4*)&q[(size_t)(t0 + t) * C_DIM + k];
        float vv[4] = {v.x, v.y, v.z, v.w};
#pragma unroll
        for (int u = 0; u < 4; u++) {
            __nv_bfloat16 h = __float2bfloat16(vv[u]);
            Bh[t * QB_STR + k + u] = h;
            Bl[t * QB_STR + k + u] = __float2bfloat16(vv[u] - __bfloat162float(h));
        }
    }
    if (tid < 128) rsum[tid] = 0.f;
    __syncthreads();

    uint32_t sBh = smem_u32(Bh), sBl = smem_u32(Bl);

    float acc[2][8][4];
#pragma unroll
    for (int mf = 0; mf < 2; mf++)
#pragma unroll
        for (int nf = 0; nf < 8; nf++)
#pragma unroll
            for (int u = 0; u < 4; u++) acc[mf][nf][u] = 0.f;

    int g = lane >> 2, t2 = (lane & 3) * 2;
    int lrow = (lane & 7) + ((lane >> 4) << 3);
    int lcol = (lane & 8);

    for (int ks = 0; ks < 16; ks++) {
        int k0 = ks * 16;
        uint32_t ah[2][4], al[2][4];
#pragma unroll
        for (int mf = 0; mf < 2; mf++) {
            int mb = m0 + mf * 16;
            ah[mf][0] = *(const uint32_t*)&g_mh[(mb + g) * C_DIM + k0 + t2];
            ah[mf][1] = *(const uint32_t*)&g_mh[(mb + g + 8) * C_DIM + k0 + t2];
            ah[mf][2] = *(const uint32_t*)&g_mh[(mb + g) * C_DIM + k0 + t2 + 8];
            ah[mf][3] = *(const uint32_t*)&g_mh[(mb + g + 8) * C_DIM + k0 + t2 + 8];
            al[mf][0] = *(const uint32_t*)&g_ml[(mb + g) * C_DIM + k0 + t2];
            al[mf][1] = *(const uint32_t*)&g_ml[(mb + g + 8) * C_DIM + k0 + t2];
            al[mf][2] = *(const uint32_t*)&g_ml[(mb + g) * C_DIM + k0 + t2 + 8];
            al[mf][3] = *(const uint32_t*)&g_ml[(mb + g + 8) * C_DIM + k0 + t2 + 8];
        }
        uint32_t bh[8][2], bl[8][2];
#pragma unroll
        for (int pr = 0; pr < 4; pr++) {
            int tb = t0w + pr * 16;
            uint32_t off = (uint32_t)((tb + lrow) * QB_STR + k0 + lcol) * 2;
            LDMATRIX_X4(bh[pr * 2][0], bh[pr * 2][1], bh[pr * 2 + 1][0], bh[pr * 2 + 1][1], sBh + off);
            LDMATRIX_X4(bl[pr * 2][0], bl[pr * 2][1], bl[pr * 2 + 1][0], bl[pr * 2 + 1][1], sBl + off);
        }
#pragma unroll
        for (int mf = 0; mf < 2; mf++)
#pragma unroll
            for (int nf = 0; nf < 8; nf++) {
                MMA_BF16(acc[mf][nf], ah[mf], bh[nf]);
                MMA_BF16(acc[mf][nf], ah[mf], bl[nf]);
                MMA_BF16(acc[mf][nf], al[mf], bh[nf]);
            }
    }

#pragma unroll
    for (int mf = 0; mf < 2; mf++) {
        float p0 = 0.f, p1 = 0.f;
        int mr0 = m0 + mf * 16 + g;
        int mr1 = mr0 + 8;
#pragma unroll
        for (int nf = 0; nf < 8; nf++) {
            int ta = t0 + t0w + nf * 8 + t2;
            float e0 = __expf(acc[mf][nf][0]);
            float e1 = __expf(acc[mf][nf][1]);
            float e2 = __expf(acc[mf][nf][2]);
            float e3 = __expf(acc[mf][nf][3]);
            *(float2*)&g_S[(size_t)mr0 * T_TOT + ta] = make_float2(e0, e1);
            *(float2*)&g_S[(size_t)mr1 * T_TOT + ta] = make_float2(e2, e3);
            p0 += e0 + e1;
            p1 += e2 + e3;
        }
#pragma unroll
        for (int o = 1; o < 4; o <<= 1) {
            p0 += __shfl_xor_sync(0xffffffffu, p0, o);
            p1 += __shfl_xor_sync(0xffffffffu, p1, o);
        }
        if ((lane & 3) == 0) {
            atomicAdd(&rsum[mr0], p0);
            atomicAdd(&rsum[mr1], p1);
        }
    }
    __syncthreads();
    if (tid < 128) atomicAdd(&g_rowsum[tid], rsum[tid]);
}

// ---------------- K2: scan survivors + shrink + l1 ----------------
__global__ __launch_bounds__(256) void k2_scan() {
    int m = blockIdx.y;
    float rs = g_rowsum[m];
    float thr = SHRINKV * rs;
    float inv = 1.0f / rs;
    size_t rowbase = (size_t)m * T_TOT;
    int tbase = blockIdx.x * 16384 + threadIdx.x * 4;
#pragma unroll
    for (int j = 0; j < 16; j++) {
        int t = tbase + j * 1024;
        float4 v = *(const float4*)&g_S[rowbase + t];
        float e[4] = {v.x, v.y, v.z, v.w};
#pragma unroll
        for (int k = 0; k < 4; k++) {
            if (e[k] > thr) {
                float a = e[k] * inv;
                float d = a - SHRINKV;
                float h = (d > 0.f) ? d * a / (d + EPSV) : 0.f;
                unsigned int pos = atomicAdd(&g_cnt, 1u);
                if (pos < LIST_CAP) {
                    g_key[pos] = ((unsigned int)(t + k) << 7) | (unsigned int)m;
                    g_val[pos] = h;
                }
                atomicAdd(&g_l1[m], h);
            }
        }
    }
}

// ---------------- K3 ----------------
__global__ __launch_bounds__(256) void k3_scatter(const float* __restrict__ q) {
    unsigned int n = g_cnt; if (n > LIST_CAP) n = LIST_CAP;
    int c = threadIdx.x;
    for (unsigned int i = blockIdx.x; i < n; i += gridDim.x) {
        unsigned int key = g_key[i];
        unsigned int t = key >> 7, m = key & 127;
        float h = g_val[i];
        atomicAdd(&g_addmem[m * C_DIM + c], h * q[(size_t)t * C_DIM + c]);
    }
}

// ---------------- K4 ----------------
__global__ __launch_bounds__(256) void k4_gate(const float* __restrict__ mem,
                                               const float* __restrict__ Uw,
                                               const float* __restrict__ Ub,
                                               const float* __restrict__ Ww,
                                               const float* __restrict__ Wb,
                                               float* __restrict__ nm_out) {
    __shared__ float mr[8][256], ar[8][256];
    int c = threadIdx.x;
    int m0 = blockIdx.x * 8;

    for (int i = 0; i < 8; i++) {
        int m = m0 + i;
        float invl1 = 1.0f / fmaxf(g_l1[m], EPSV);
        mr[i][c] = mem[m * C_DIM + c];
        ar[i][c] = g_addmem[m * C_DIM + c] * invl1;
    }
    __syncthreads();

    float s[8];
    float b = Ub[c] + Wb[c];
#pragma unroll
    for (int i = 0; i < 8; i++) s[i] = b;

    const float* uw = Uw + c * C_DIM;
    const float* ww = Ww + c * C_DIM;
#pragma unroll 4
    for (int k = 0; k < C_DIM; k++) {
        float wu = uw[k], wv = ww[k];
#pragma unroll
        for (int i = 0; i < 8; i++)
            s[i] += mr[i][k] * wu + ar[i][k] * wv;
    }
#pragma unroll
    for (int i = 0; i < 8; i++) {
        int m = m0 + i;
        float g = 1.f / (1.f + __expf(-s[i]));
        float nm = (1.f - g) * mr[i][c] + g * ar[i][c];
        g_newmem[m * C_DIM + c] = nm;
        nm_out[m * C_DIM + c] = nm;
    }
}

// ---------------- K5: fused read phase via mma.sync (register-resident per warp) ----------------
// block: 128 tokens, 256 threads (8 warps, 16 tokens each). nm bf16 hi/lo in smem [128][264].
#define NMS 264
__global__ __launch_bounds__(256) void k5_mma(const float* __restrict__ q,
                                              float* __restrict__ out,
                                              float* __restrict__ attn) {
    extern __shared__ __nv_bfloat16 sm5[];
    __nv_bfloat16* Nh = sm5;               // [128][264]
    __nv_bfloat16* Nl = sm5 + 128 * NMS;

    int tid = threadIdx.x, lane = tid & 31, warp = tid >> 5;
    size_t T0 = (size_t)blockIdx.x * 128;

    // stage new_mem -> bf16 hi/lo smem
    for (int i = tid * 2; i < 128 * 256; i += 512) {
        int m = i >> 8, c = i & 255;
        float2 v = *(const float2*)&g_newmem[i];
        uint32_t hi, lo;
        split2(v.x, v.y, hi, lo);
        *(uint32_t*)&Nh[m * NMS + c] = hi;
        *(uint32_t*)&Nl[m * NMS + c] = lo;
    }
    // q copy -> out[:, 0:256]
    for (int l = tid * 4; l < 128 * 256; l += 1024) {
        int t = l >> 8, c = l & 255;
        float4 v = *(const float4*)&q[T0 * C_DIM + l];
        *(float4*)&out[(T0 + t) * 512 + c] = v;
    }
    __syncthreads();

    uint32_t sNh = smem_u32(Nh), sNl = smem_u32(Nl);

    int g = lane >> 2, t2 = (lane & 3) * 2;
    int lrow = (lane & 7) + ((lane >> 4) << 3);
    int lcol = (lane & 8);
    int tw = warp * 16;
    size_t rowg = T0 + tw + g;       // token row for c0,c1
    size_t rowg8 = rowg + 8;         // token row for c2,c3

    // ==== phase 1: scores 16t x 128m ====
    float acc[16][4];
#pragma unroll
    for (int j = 0; j < 16; j++)
#pragma unroll
        for (int u = 0; u < 4; u++) acc[j][u] = 0.f;

    for (int ks = 0; ks < 16; ks++) {
        int k0 = ks * 16;
        // a-frags from q (global), bf16 split in-reg
        float2 f0 = *(const float2*)&q[rowg * C_DIM + k0 + t2];
        float2 f1 = *(const float2*)&q[rowg8 * C_DIM + k0 + t2];
        float2 f2 = *(const float2*)&q[rowg * C_DIM + k0 + t2 + 8];
        float2 f3 = *(const float2*)&q[rowg8 * C_DIM + k0 + t2 + 8];
        uint32_t ah[4], al[4];
        split2(f0.x, f0.y, ah[0], al[0]);
        split2(f1.x, f1.y, ah[1], al[1]);
        split2(f2.x, f2.y, ah[2], al[2]);
        split2(f3.x, f3.y, ah[3], al[3]);

#pragma unroll
        for (int bp = 0; bp < 8; bp++) {
            uint32_t off = (uint32_t)((16 * bp + lrow) * NMS + k0 + lcol) * 2;
            uint32_t h0, h1, h2, h3, l0, l1, l2, l3;
            LDMATRIX_X4(h0, h1, h2, h3, sNh + off);
            LDMATRIX_X4(l0, l1, l2, l3, sNl + off);
            uint32_t bh0[2] = {h0, h1}, bh1[2] = {h2, h3};
            uint32_t bl0[2] = {l0, l1}, bl1[2] = {l2, l3};
            MMA_BF16(acc[2 * bp], ah, bh0);
            MMA_BF16(acc[2 * bp], ah, bl0);
            MMA_BF16(acc[2 * bp], al, bh0);
            MMA_BF16(acc[2 * bp + 1], ah, bh1);
            MMA_BF16(acc[2 * bp + 1], ah, bl1);
            MMA_BF16(acc[2 * bp + 1], al, bh1);
        }
    }

    // ==== softmax + shrink + l1-normalize (quad-local) ====
    {
        float mx0 = -1e30f, mx1 = -1e30f;
#pragma unroll
        for (int j = 0; j < 16; j++) {
            mx0 = fmaxf(mx0, fmaxf(acc[j][0], acc[j][1]));
            mx1 = fmaxf(mx1, fmaxf(acc[j][2], acc[j][3]));
        }
#pragma unroll
        for (int o = 1; o < 4; o <<= 1) {
            mx0 = fmaxf(mx0, __shfl_xor_sync(0xffffffffu, mx0, o));
            mx1 = fmaxf(mx1, __shfl_xor_sync(0xffffffffu, mx1, o));
        }
        float s0 = 0.f, s1 = 0.f;
#pragma unroll
        for (int j = 0; j < 16; j++) {
            acc[j][0] = __expf(acc[j][0] - mx0);
            acc[j][1] = __expf(acc[j][1] - mx0);
            acc[j][2] = __expf(acc[j][2] - mx1);
            acc[j][3] = __expf(acc[j][3] - mx1);
            s0 += acc[j][0] + acc[j][1];
            s1 += acc[j][2] + acc[j][3];
        }
#pragma unroll
        for (int o = 1; o < 4; o <<= 1) {
            s0 += __shfl_xor_sync(0xffffffffu, s0, o);
            s1 += __shfl_xor_sync(0xffffffffu, s1, o);
        }
        float i0 = 1.f / s0, i1 = 1.f / s1;
        float l10 = 0.f, l11 = 0.f;
#pragma unroll
        for (int j = 0; j < 16; j++) {
            float a0 = acc[j][0] * i0, a1 = acc[j][1] * i0;
            float a2 = acc[j][2] * i1, a3 = acc[j][3] * i1;
            float d0 = a0 - SHRINKV, d1 = a1 - SHRINKV;
            float d2 = a2 - SHRINKV, d3 = a3 - SHRINKV;
            acc[j][0] = (d0 > 0.f) ? __fdividef(d0 * a0, d0 + EPSV) : 0.f;
            acc[j][1] = (d1 > 0.f) ? __fdividef(d1 * a1, d1 + EPSV) : 0.f;
            acc[j][2] = (d2 > 0.f) ? __fdividef(d2 * a2, d2 + EPSV) : 0.f;
            acc[j][3] = (d3 > 0.f) ? __fdividef(d3 * a3, d3 + EPSV) : 0.f;
            l10 += acc[j][0] + acc[j][1];
            l11 += acc[j][2] + acc[j][3];
        }
#pragma unroll
        for (int o = 1; o < 4; o <<= 1) {
            l10 += __shfl_xor_sync(0xffffffffu, l10, o);
            l11 += __shfl_xor_sync(0xffffffffu, l11, o);
        }
        float n0 = 1.f / fmaxf(l10, EPSV), n1 = 1.f / fmaxf(l11, EPSV);
#pragma unroll
        for (int j = 0; j < 16; j++) {
            acc[j][0] *= n0; acc[j][1] *= n0;
            acc[j][2] *= n1; acc[j][3] *= n1;
            int mm = 8 * j + t2;
            *(float2*)&attn[rowg * M_DIM + mm] = make_float2(acc[j][0], acc[j][1]);
            *(float2*)&attn[rowg8 * M_DIM + mm] = make_float2(acc[j][2], acc[j][3]);
        }
    }

    // ==== h (c-frag) -> a-frags bf16 hi/lo for phase 2 ====
    uint32_t hh[8][4], hl[8][4];
#pragma unroll
    for (int s = 0; s < 8; s++) {
        split2(acc[2 * s][0], acc[2 * s][1], hh[s][0], hl[s][0]);
        split2(acc[2 * s][2], acc[2 * s][3], hh[s][1], hl[s][1]);
        split2(acc[2 * s + 1][0], acc[2 * s + 1][1], hh[s][2], hl[s][2]);
        split2(acc[2 * s + 1][2], acc[2 * s + 1][3], hh[s][3], hl[s][3]);
    }

    // ==== phase 2: add_memory 16t x 256c (two 128c passes), k = 128 m ====
#pragma unroll
    for (int p = 0; p < 2; p++) {
        float ac2[16][4];
#pragma unroll
        for (int j = 0; j < 16; j++)
#pragma unroll
            for (int u = 0; u < 4; u++) ac2[j][u] = 0.f;

#pragma unroll
        for (int s = 0; s < 8; s++) {
#pragma unroll
            for (int np = 0; np < 8; np++) {
                uint32_t off = (uint32_t)((16 * s + (lane & 15)) * NMS
                              + p * 128 + np * 16 + ((lane >> 4) * 8)) * 2;
                uint32_t h0, h1, h2, h3, l0, l1, l2, l3;
                LDMATRIX_X4T(h0, h1, h2, h3, sNh + off);
                LDMATRIX_X4T(l0, l1, l2, l3, sNl + off);
                uint32_t bh0[2] = {h0, h1}, bh1[2] = {h2, h3};
                uint32_t bl0[2] = {l0, l1}, bl1[2] = {l2, l3};
                MMA_BF16(ac2[2 * np], hh[s], bh0);
                MMA_BF16(ac2[2 * np], hh[s], bl0);
                MMA_BF16(ac2[2 * np], hl[s], bh0);
                MMA_BF16(ac2[2 * np + 1], hh[s], bh1);
                MMA_BF16(ac2[2 * np + 1], hh[s], bl1);
                MMA_BF16(ac2[2 * np + 1], hl[s], bh1);
            }
        }
#pragma unroll
        for (int nf = 0; nf < 16; nf++) {
            int c = 256 + p * 128 + nf * 8 + t2;
            *(float2*)&out[rowg * 512 + c] = make_float2(ac2[nf][0], ac2[nf][1]);
            *(float2*)&out[rowg8 * 512 + c] = make_float2(ac2[nf][2], ac2[nf][3]);
        }
    }
}

// ---------------- launcher ----------------
extern "C" void kernel_launch(void* const* d_in, const int* in_sizes, int n_in,
                              void* d_out, int out_size) {
    const float* query = (const float*)d_in[0];
    const float* mem   = (const float*)d_in[1];
    const float* Uw    = (const float*)d_in[2];
    const float* Ub    = (const float*)d_in[3];
    const float* Ww    = (const float*)d_in[4];
    const float* Wb    = (const float*)d_in[5];

    float* out  = (float*)d_out;
    float* attn = out + (size_t)T_TOT * 512;
    float* nmo  = attn + (size_t)T_TOT * M_DIM;

    const int SMEM1 = 2 * 128 * QB_STR * 2;   // 135,168 B
    const int SMEM5 = 2 * 128 * NMS * 2;      // 135,168 B
    cudaFuncSetAttribute(k1_mma, cudaFuncAttributeMaxDynamicSharedMemorySize, SMEM1);
    cudaFuncSetAttribute(k5_mma, cudaFuncAttributeMaxDynamicSharedMemorySize, SMEM5);

    k0_init<<<128, 256>>>(mem);
    k1_mma<<<T_TOT / 128, 256, SMEM1>>>(query);
    k2_scan<<<dim3(4, 128), 256>>>();
    k3_scatter<<<64, 256>>>(query);
    k4_gate<<<16, 256>>>(mem, Uw, Ub, Ww, Wb, nmo);
    k5_mma<<<T_TOT / 128, 256, SMEM5>>>(query, out, attn);
}

// round 11
// speedup vs baseline: 2.6941x; 1.4228x over previous
#include <cuda_runtime.h>
#include <cuda_bf16.h>
#include <cstdint>
#include <math.h>

#define T_TOT 65536
#define C_DIM 256
#define M_DIM 128
#define SHRINKV 0.0025f
#define EPSV 1e-12f
#define LIST_CAP 4194304

typedef unsigned long long ull;

__device__ __forceinline__ uint32_t smem_u32(const void* p) {
    uint32_t a;
    asm("{ .reg .u64 t; cvta.to.shared.u64 t, %1; cvt.u32.u64 %0, t; }" : "=r"(a) : "l"(p));
    return a;
}
#define LDMATRIX_X4(r0, r1, r2, r3, addr) \
    asm volatile("ldmatrix.sync.aligned.m8n8.x4.shared.b16 {%0,%1,%2,%3}, [%4];" \
        : "=r"(r0), "=r"(r1), "=r"(r2), "=r"(r3) : "r"(addr))
#define LDMATRIX_X4T(r0, r1, r2, r3, addr) \
    asm volatile("ldmatrix.sync.aligned.m8n8.x4.trans.shared.b16 {%0,%1,%2,%3}, [%4];" \
        : "=r"(r0), "=r"(r1), "=r"(r2), "=r"(r3) : "r"(addr))
// NOTE: no volatile — pure register dataflow, let ptxas interleave
#define MMA_BF16(acc, a, b) \
    asm("mma.sync.aligned.m16n8k16.row.col.f32.bf16.bf16.f32 " \
        "{%0,%1,%2,%3}, {%4,%5,%6,%7}, {%8,%9}, {%0,%1,%2,%3};" \
        : "+f"((acc)[0]), "+f"((acc)[1]), "+f"((acc)[2]), "+f"((acc)[3]) \
        : "r"((a)[0]), "r"((a)[1]), "r"((a)[2]), "r"((a)[3]), "r"((b)[0]), "r"((b)[1]))

__device__ __forceinline__ uint32_t bfpair(float x, float y) {
    __nv_bfloat162 p = __floats2bfloat162_rn(x, y);
    return *(uint32_t*)&p;
}
__device__ __forceinline__ float bf_lo_f(uint32_t p) {
    return __uint_as_float((p & 0xFFFFu) << 16);
}
__device__ __forceinline__ float bf_hi_f(uint32_t p) {
    return __uint_as_float(p & 0xFFFF0000u);
}
__device__ __forceinline__ void split2(float x, float y, uint32_t& hi, uint32_t& lo) {
    hi = bfpair(x, y);
    lo = bfpair(x - bf_lo_f(hi), y - bf_hi_f(hi));
}

// ---------------- scratch ----------------
__device__ float g_S[(size_t)M_DIM * T_TOT];
__device__ float g_rowsum[M_DIM];
__device__ float g_l1[M_DIM];
__device__ float g_addmem[M_DIM * C_DIM];
__device__ float g_newmem[M_DIM * C_DIM];
__device__ unsigned int g_cnt;
__device__ unsigned int g_key[LIST_CAP];
__device__ float g_val[LIST_CAP];
__device__ __nv_bfloat16 g_mh[M_DIM * C_DIM];
__device__ __nv_bfloat16 g_ml[M_DIM * C_DIM];

// ---------------- K0 ----------------
__global__ void k0_init(const float* __restrict__ mem) {
    int i = blockIdx.x * blockDim.x + threadIdx.x;
    if (i < M_DIM) { g_rowsum[i] = 0.f; g_l1[i] = 0.f; }
    if (i == 0) g_cnt = 0u;
    float v = mem[i];
    __nv_bfloat16 h = __float2bfloat16(v);
    g_mh[i] = h;
    g_ml[i] = __float2bfloat16(v - __bfloat162float(h));
    if (i < M_DIM * C_DIM) g_addmem[i] = 0.f;
}

// ---------------- K1: S[m][t] = exp(mem[m].q[t]) via mma.sync, pass-major ----------------
#define QB_STR 264
__global__ __launch_bounds__(256) void k1_mma(const float* __restrict__ q) {
    extern __shared__ __nv_bfloat16 qsm[];
    __nv_bfloat16* Bh = qsm;
    __nv_bfloat16* Bl = qsm + 128 * QB_STR;
    __shared__ float rsum[128];

    int tid = threadIdx.x, lane = tid & 31, warp = tid >> 5;
    int t0 = blockIdx.x * 128;
    int m0 = (warp >> 1) * 32;
    int t0w = (warp & 1) * 64;

    for (int i = tid * 4; i < 128 * 256; i += 1024) {
        int t = i >> 8, k = i & 255;
        float4 v = *(const float4*)&q[(size_t)(t0 + t) * C_DIM + k];
        float vv[4] = {v.x, v.y, v.z, v.w};
#pragma unroll
        for (int u = 0; u < 4; u++) {
            __nv_bfloat16 h = __float2bfloat16(vv[u]);
            Bh[t * QB_STR + k + u] = h;
            Bl[t * QB_STR + k + u] = __float2bfloat16(vv[u] - __bfloat162float(h));
        }
    }
    if (tid < 128) rsum[tid] = 0.f;
    __syncthreads();

    uint32_t sBh = smem_u32(Bh), sBl = smem_u32(Bl);

    float acc[2][8][4];
#pragma unroll
    for (int mf = 0; mf < 2; mf++)
#pragma unroll
        for (int nf = 0; nf < 8; nf++)
#pragma unroll
            for (int u = 0; u < 4; u++) acc[mf][nf][u] = 0.f;

    int g = lane >> 2, t2 = (lane & 3) * 2;
    int lrow = (lane & 7) + ((lane >> 4) << 3);
    int lcol = (lane & 8);

    for (int ks = 0; ks < 16; ks++) {
        int k0 = ks * 16;
        uint32_t ah[2][4], al[2][4];
#pragma unroll
        for (int mf = 0; mf < 2; mf++) {
            int mb = m0 + mf * 16;
            ah[mf][0] = *(const uint32_t*)&g_mh[(mb + g) * C_DIM + k0 + t2];
            ah[mf][1] = *(const uint32_t*)&g_mh[(mb + g + 8) * C_DIM + k0 + t2];
            ah[mf][2] = *(const uint32_t*)&g_mh[(mb + g) * C_DIM + k0 + t2 + 8];
            ah[mf][3] = *(const uint32_t*)&g_mh[(mb + g + 8) * C_DIM + k0 + t2 + 8];
            al[mf][0] = *(const uint32_t*)&g_ml[(mb + g) * C_DIM + k0 + t2];
            al[mf][1] = *(const uint32_t*)&g_ml[(mb + g + 8) * C_DIM + k0 + t2];
            al[mf][2] = *(const uint32_t*)&g_ml[(mb + g) * C_DIM + k0 + t2 + 8];
            al[mf][3] = *(const uint32_t*)&g_ml[(mb + g + 8) * C_DIM + k0 + t2 + 8];
        }
        uint32_t bh[8][2], bl[8][2];
#pragma unroll
        for (int pr = 0; pr < 4; pr++) {
            int tb = t0w + pr * 16;
            uint32_t off = (uint32_t)((tb + lrow) * QB_STR + k0 + lcol) * 2;
            LDMATRIX_X4(bh[pr * 2][0], bh[pr * 2][1], bh[pr * 2 + 1][0], bh[pr * 2 + 1][1], sBh + off);
            LDMATRIX_X4(bl[pr * 2][0], bl[pr * 2][1], bl[pr * 2 + 1][0], bl[pr * 2 + 1][1], sBl + off);
        }
        // pass-major: 16 independent MMAs between accumulator reuses
#pragma unroll
        for (int mf = 0; mf < 2; mf++)
#pragma unroll
            for (int nf = 0; nf < 8; nf++) MMA_BF16(acc[mf][nf], ah[mf], bh[nf]);
#pragma unroll
        for (int mf = 0; mf < 2; mf++)
#pragma unroll
            for (int nf = 0; nf < 8; nf++) MMA_BF16(acc[mf][nf], ah[mf], bl[nf]);
#pragma unroll
        for (int mf = 0; mf < 2; mf++)
#pragma unroll
            for (int nf = 0; nf < 8; nf++) MMA_BF16(acc[mf][nf], al[mf], bh[nf]);
    }

#pragma unroll
    for (int mf = 0; mf < 2; mf++) {
        float p0 = 0.f, p1 = 0.f;
        int mr0 = m0 + mf * 16 + g;
        int mr1 = mr0 + 8;
#pragma unroll
        for (int nf = 0; nf < 8; nf++) {
            int ta = t0 + t0w + nf * 8 + t2;
            float e0 = __expf(acc[mf][nf][0]);
            float e1 = __expf(acc[mf][nf][1]);
            float e2 = __expf(acc[mf][nf][2]);
            float e3 = __expf(acc[mf][nf][3]);
            *(float2*)&g_S[(size_t)mr0 * T_TOT + ta] = make_float2(e0, e1);
            *(float2*)&g_S[(size_t)mr1 * T_TOT + ta] = make_float2(e2, e3);
            p0 += e0 + e1;
            p1 += e2 + e3;
        }
#pragma unroll
        for (int o = 1; o < 4; o <<= 1) {
            p0 += __shfl_xor_sync(0xffffffffu, p0, o);
            p1 += __shfl_xor_sync(0xffffffffu, p1, o);
        }
        if ((lane & 3) == 0) {
            atomicAdd(&rsum[mr0], p0);
            atomicAdd(&rsum[mr1], p1);
        }
    }
    __syncthreads();
    if (tid < 128) atomicAdd(&g_rowsum[tid], rsum[tid]);
}

// ---------------- K2: scan survivors + shrink + l1 ----------------
__global__ __launch_bounds__(256) void k2_scan() {
    int m = blockIdx.y;
    float rs = g_rowsum[m];
    float thr = SHRINKV * rs;
    float inv = 1.0f / rs;
    size_t rowbase = (size_t)m * T_TOT;
    int tbase = blockIdx.x * 16384 + threadIdx.x * 4;
#pragma unroll
    for (int j = 0; j < 16; j++) {
        int t = tbase + j * 1024;
        float4 v = *(const float4*)&g_S[rowbase + t];
        float e[4] = {v.x, v.y, v.z, v.w};
#pragma unroll
        for (int k = 0; k < 4; k++) {
            if (e[k] > thr) {
                float a = e[k] * inv;
                float d = a - SHRINKV;
                float h = (d > 0.f) ? d * a / (d + EPSV) : 0.f;
                unsigned int pos = atomicAdd(&g_cnt, 1u);
                if (pos < LIST_CAP) {
                    g_key[pos] = ((unsigned int)(t + k) << 7) | (unsigned int)m;
                    g_val[pos] = h;
                }
                atomicAdd(&g_l1[m], h);
            }
        }
    }
}

// ---------------- K3 ----------------
__global__ __launch_bounds__(256) void k3_scatter(const float* __restrict__ q) {
    unsigned int n = g_cnt; if (n > LIST_CAP) n = LIST_CAP;
    int c = threadIdx.x;
    for (unsigned int i = blockIdx.x; i < n; i += gridDim.x) {
        unsigned int key = g_key[i];
        unsigned int t = key >> 7, m = key & 127;
        float h = g_val[i];
        atomicAdd(&g_addmem[m * C_DIM + c], h * q[(size_t)t * C_DIM + c]);
    }
}

// ---------------- K4 ----------------
__global__ __launch_bounds__(256) void k4_gate(const float* __restrict__ mem,
                                               const float* __restrict__ Uw,
                                               const float* __restrict__ Ub,
                                               const float* __restrict__ Ww,
                                               const float* __restrict__ Wb,
                                               float* __restrict__ nm_out) {
    __shared__ float mr[8][256], ar[8][256];
    int c = threadIdx.x;
    int m0 = blockIdx.x * 8;

    for (int i = 0; i < 8; i++) {
        int m = m0 + i;
        float invl1 = 1.0f / fmaxf(g_l1[m], EPSV);
        mr[i][c] = mem[m * C_DIM + c];
        ar[i][c] = g_addmem[m * C_DIM + c] * invl1;
    }
    __syncthreads();

    float s[8];
    float b = Ub[c] + Wb[c];
#pragma unroll
    for (int i = 0; i < 8; i++) s[i] = b;

    const float* uw = Uw + c * C_DIM;
    const float* ww = Ww + c * C_DIM;
#pragma unroll 4
    for (int k = 0; k < C_DIM; k++) {
        float wu = uw[k], wv = ww[k];
#pragma unroll
        for (int i = 0; i < 8; i++)
            s[i] += mr[i][k] * wu + ar[i][k] * wv;
    }
#pragma unroll
    for (int i = 0; i < 8; i++) {
        int m = m0 + i;
        float g = 1.f / (1.f + __expf(-s[i]));
        float nm = (1.f - g) * mr[i][c] + g * ar[i][c];
        g_newmem[m * C_DIM + c] = nm;
        nm_out[m * C_DIM + c] = nm;
    }
}

// ---------------- K5: fused read phase via mma.sync, pass-major ----------------
#define NMS 264
__global__ __launch_bounds__(256) void k5_mma(const float* __restrict__ q,
                                              float* __restrict__ out,
                                              float* __restrict__ attn) {
    extern __shared__ __nv_bfloat16 sm5[];
    __nv_bfloat16* Nh = sm5;
    __nv_bfloat16* Nl = sm5 + 128 * NMS;

    int tid = threadIdx.x, lane = tid & 31, warp = tid >> 5;
    size_t T0 = (size_t)blockIdx.x * 128;

    for (int i = tid * 2; i < 128 * 256; i += 512) {
        int m = i >> 8, c = i & 255;
        float2 v = *(const float2*)&g_newmem[i];
        uint32_t hi, lo;
        split2(v.x, v.y, hi, lo);
        *(uint32_t*)&Nh[m * NMS + c] = hi;
        *(uint32_t*)&Nl[m * NMS + c] = lo;
    }
    for (int l = tid * 4; l < 128 * 256; l += 1024) {
        int t = l >> 8, c = l & 255;
        float4 v = *(const float4*)&q[T0 * C_DIM + l];
        *(float4*)&out[(T0 + t) * 512 + c] = v;
    }
    __syncthreads();

    uint32_t sNh = smem_u32(Nh), sNl = smem_u32(Nl);

    int g = lane >> 2, t2 = (lane & 3) * 2;
    int lrow = (lane & 7) + ((lane >> 4) << 3);
    int lcol = (lane & 8);
    int tw = warp * 16;
    size_t rowg = T0 + tw + g;
    size_t rowg8 = rowg + 8;

    // ==== phase 1: scores 16t x 128m ====
    float acc[16][4];
#pragma unroll
    for (int j = 0; j < 16; j++)
#pragma unroll
        for (int u = 0; u < 4; u++) acc[j][u] = 0.f;

    for (int ks = 0; ks < 16; ks++) {
        int k0 = ks * 16;
        float2 f0 = *(const float2*)&q[rowg * C_DIM + k0 + t2];
        float2 f1 = *(const float2*)&q[rowg8 * C_DIM + k0 + t2];
        float2 f2 = *(const float2*)&q[rowg * C_DIM + k0 + t2 + 8];
        float2 f3 = *(const float2*)&q[rowg8 * C_DIM + k0 + t2 + 8];
        uint32_t ah[4], al[4];
        split2(f0.x, f0.y, ah[0], al[0]);
        split2(f1.x, f1.y, ah[1], al[1]);
        split2(f2.x, f2.y, ah[2], al[2]);
        split2(f3.x, f3.y, ah[3], al[3]);

        uint32_t bh[16][2], bl[16][2];
#pragma unroll
        for (int bp = 0; bp < 8; bp++) {
            uint32_t off = (uint32_t)((16 * bp + lrow) * NMS + k0 + lcol) * 2;
            LDMATRIX_X4(bh[2 * bp][0], bh[2 * bp][1], bh[2 * bp + 1][0], bh[2 * bp + 1][1], sNh + off);
            LDMATRIX_X4(bl[2 * bp][0], bl[2 * bp][1], bl[2 * bp + 1][0], bl[2 * bp + 1][1], sNl + off);
        }
        // pass-major
#pragma unroll
        for (int j = 0; j < 16; j++) MMA_BF16(acc[j], ah, bh[j]);
#pragma unroll
        for (int j = 0; j < 16; j++) MMA_BF16(acc[j], ah, bl[j]);
#pragma unroll
        for (int j = 0; j < 16; j++) MMA_BF16(acc[j], al, bh[j]);
    }

    // ==== softmax + shrink + l1-normalize (quad-local) ====
    {
        float mx0 = -1e30f, mx1 = -1e30f;
#pragma unroll
        for (int j = 0; j < 16; j++) {
            mx0 = fmaxf(mx0, fmaxf(acc[j][0], acc[j][1]));
            mx1 = fmaxf(mx1, fmaxf(acc[j][2], acc[j][3]));
        }
#pragma unroll
        for (int o = 1; o < 4; o <<= 1) {
            mx0 = fmaxf(mx0, __shfl_xor_sync(0xffffffffu, mx0, o));
            mx1 = fmaxf(mx1, __shfl_xor_sync(0xffffffffu, mx1, o));
        }
        float s0 = 0.f, s1 = 0.f;
#pragma unroll
        for (int j = 0; j < 16; j++) {
            acc[j][0] = __expf(acc[j][0] - mx0);
            acc[j][1] = __expf(acc[j][1] - mx0);
            acc[j][2] = __expf(acc[j][2] - mx1);
            acc[j][3] = __expf(acc[j][3] - mx1);
            s0 += acc[j][0] + acc[j][1];
            s1 += acc[j][2] + acc[j][3];
        }
#pragma unroll
        for (int o = 1; o < 4; o <<= 1) {
            s0 += __shfl_xor_sync(0xffffffffu, s0, o);
            s1 += __shfl_xor_sync(0xffffffffu, s1, o);
        }
        float i0 = 1.f / s0, i1 = 1.f / s1;
        float l10 = 0.f, l11 = 0.f;
#pragma unroll
        for (int j = 0; j < 16; j++) {
            float a0 = acc[j][0] * i0, a1 = acc[j][1] * i0;
            float a2 = acc[j][2] * i1, a3 = acc[j][3] * i1;
            float d0 = a0 - SHRINKV, d1 = a1 - SHRINKV;
            float d2 = a2 - SHRINKV, d3 = a3 - SHRINKV;
            acc[j][0] = (d0 > 0.f) ? __fdividef(d0 * a0, d0 + EPSV) : 0.f;
            acc[j][1] = (d1 > 0.f) ? __fdividef(d1 * a1, d1 + EPSV) : 0.f;
            acc[j][2] = (d2 > 0.f) ? __fdividef(d2 * a2, d2 + EPSV) : 0.f;
            acc[j][3] = (d3 > 0.f) ? __fdividef(d3 * a3, d3 + EPSV) : 0.f;
            l10 += acc[j][0] + acc[j][1];
            l11 += acc[j][2] + acc[j][3];
        }
#pragma unroll
        for (int o = 1; o < 4; o <<= 1) {
            l10 += __shfl_xor_sync(0xffffffffu, l10, o);
            l11 += __shfl_xor_sync(0xffffffffu, l11, o);
        }
        float n0 = 1.f / fmaxf(l10, EPSV), n1 = 1.f / fmaxf(l11, EPSV);
#pragma unroll
        for (int j = 0; j < 16; j++) {
            acc[j][0] *= n0; acc[j][1] *= n0;
            acc[j][2] *= n1; acc[j][3] *= n1;
            int mm = 8 * j + t2;
            *(float2*)&attn[rowg * M_DIM + mm] = make_float2(acc[j][0], acc[j][1]);
            *(float2*)&attn[rowg8 * M_DIM + mm] = make_float2(acc[j][2], acc[j][3]);
        }
    }

    // ==== h -> a-frags bf16 hi/lo ====
    uint32_t hh[8][4], hl[8][4];
#pragma unroll
    for (int s = 0; s < 8; s++) {
        split2(acc[2 * s][0], acc[2 * s][1], hh[s][0], hl[s][0]);
        split2(acc[2 * s][2], acc[2 * s][3], hh[s][1], hl[s][1]);
        split2(acc[2 * s + 1][0], acc[2 * s + 1][1], hh[s][2], hl[s][2]);
        split2(acc[2 * s + 1][2], acc[2 * s + 1][3], hh[s][3], hl[s][3]);
    }

    // ==== phase 2: add_memory 16t x 256c (two 128c passes) ====
#pragma unroll
    for (int p = 0; p < 2; p++) {
        float ac2[16][4];
#pragma unroll
        for (int j = 0; j < 16; j++)
#pragma unroll
            for (int u = 0; u < 4; u++) ac2[j][u] = 0.f;

#pragma unroll
        for (int s = 0; s < 8; s++) {
            uint32_t bh[16][2], bl[16][2];
#pragma unroll
            for (int np = 0; np < 8; np++) {
                uint32_t off = (uint32_t)((16 * s + (lane & 15)) * NMS
                              + p * 128 + np * 16 + ((lane >> 4) * 8)) * 2;
                LDMATRIX_X4T(bh[2 * np][0], bh[2 * np][1], bh[2 * np + 1][0], bh[2 * np + 1][1], sNh + off);
                LDMATRIX_X4T(bl[2 * np][0], bl[2 * np][1], bl[2 * np + 1][0], bl[2 * np + 1][1], sNl + off);
            }
            // pass-major
#pragma unroll
            for (int j = 0; j < 16; j++) MMA_BF16(ac2[j], hh[s], bh[j]);
#pragma unroll
            for (int j = 0; j < 16; j++) MMA_BF16(ac2[j], hh[s], bl[j]);
#pragma unroll
            for (int j = 0; j < 16; j++) MMA_BF16(ac2[j], hl[s], bh[j]);
        }
#pragma unroll
        for (int nf = 0; nf < 16; nf++) {
            int c = 256 + p * 128 + nf * 8 + t2;
            *(float2*)&out[rowg * 512 + c] = make_float2(ac2[nf][0], ac2[nf][1]);
            *(float2*)&out[rowg8 * 512 + c] = make_float2(ac2[nf][2], ac2[nf][3]);
        }
    }
}

// ---------------- launcher ----------------
extern "C" void kernel_launch(void* const* d_in, const int* in_sizes, int n_in,
                              void* d_out, int out_size) {
    const float* query = (const float*)d_in[0];
    const float* mem   = (const float*)d_in[1];
    const float* Uw    = (const float*)d_in[2];
    const float* Ub    = (const float*)d_in[3];
    const float* Ww    = (const float*)d_in[4];
    const float* Wb    = (const float*)d_in[5];

    float* out  = (float*)d_out;
    float* attn = out + (size_t)T_TOT * 512;
    float* nmo  = attn + (size_t)T_TOT * M_DIM;

    const int SMEM1 = 2 * 128 * QB_STR * 2;
    const int SMEM5 = 2 * 128 * NMS * 2;
    cudaFuncSetAttribute(k1_mma, cudaFuncAttributeMaxDynamicSharedMemorySize, SMEM1);
    cudaFuncSetAttribute(k5_mma, cudaFuncAttributeMaxDynamicSharedMemorySize, SMEM5);

    k0_init<<<128, 256>>>(mem);
    k1_mma<<<T_TOT / 128, 256, SMEM1>>>(query);
    k2_scan<<<dim3(4, 128), 256>>>();
    k3_scatter<<<64, 256>>>(query);
    k4_gate<<<16, 256>>>(mem, Uw, Ub, Ww, Wb, nmo);
    k5_mma<<<T_TOT / 128, 256, SMEM5>>>(query, out, attn);
}

// round 12
// speedup vs baseline: 3.5052x; 1.3011x over previous
#include <cuda_runtime.h>
#include <cuda_bf16.h>
#include <cstdint>
#include <math.h>

#define T_TOT 65536
#define C_DIM 256
#define M_DIM 128
#define SHRINKV 0.0025f
#define EPSV 1e-12f

typedef unsigned long long ull;

__device__ __forceinline__ uint32_t smem_u32(const void* p) {
    uint32_t a;
    asm("{ .reg .u64 t; cvta.to.shared.u64 t, %1; cvt.u32.u64 %0, t; }" : "=r"(a) : "l"(p));
    return a;
}
#define LDMATRIX_X4(r0, r1, r2, r3, addr) \
    asm volatile("ldmatrix.sync.aligned.m8n8.x4.shared.b16 {%0,%1,%2,%3}, [%4];" \
        : "=r"(r0), "=r"(r1), "=r"(r2), "=r"(r3) : "r"(addr))
#define LDMATRIX_X4T(r0, r1, r2, r3, addr) \
    asm volatile("ldmatrix.sync.aligned.m8n8.x4.trans.shared.b16 {%0,%1,%2,%3}, [%4];" \
        : "=r"(r0), "=r"(r1), "=r"(r2), "=r"(r3) : "r"(addr))
#define MMA_BF16(acc, a, b) \
    asm("mma.sync.aligned.m16n8k16.row.col.f32.bf16.bf16.f32 " \
        "{%0,%1,%2,%3}, {%4,%5,%6,%7}, {%8,%9}, {%0,%1,%2,%3};" \
        : "+f"((acc)[0]), "+f"((acc)[1]), "+f"((acc)[2]), "+f"((acc)[3]) \
        : "r"((a)[0]), "r"((a)[1]), "r"((a)[2]), "r"((a)[3]), "r"((b)[0]), "r"((b)[1]))

__device__ __forceinline__ uint32_t bfpair(float x, float y) {
    __nv_bfloat162 p = __floats2bfloat162_rn(x, y);
    return *(uint32_t*)&p;
}
__device__ __forceinline__ float bf_lo_f(uint32_t p) {
    return __uint_as_float((p & 0xFFFFu) << 16);
}
__device__ __forceinline__ float bf_hi_f(uint32_t p) {
    return __uint_as_float(p & 0xFFFF0000u);
}
__device__ __forceinline__ void split2(float x, float y, uint32_t& hi, uint32_t& lo) {
    hi = bfpair(x, y);
    lo = bfpair(x - bf_lo_f(hi), y - bf_hi_f(hi));
}

// ---------------- scratch ----------------
__device__ float g_S[(size_t)M_DIM * T_TOT];      // exp(scores), [m][t]
__device__ float g_rowpart[512 * M_DIM];          // per-block rowsum partials
__device__ float g_l1[M_DIM];
__device__ float g_addmem[M_DIM * C_DIM];
__device__ float g_newmem[M_DIM * C_DIM];

// ---------------- K1: S[m][t] = exp(mem[m].q[t]); rowsum partials; init duty ----------------
#define QB_STR 264
__global__ __launch_bounds__(256) void k1_mma(const float* __restrict__ q,
                                              const float* __restrict__ mem) {
    extern __shared__ __nv_bfloat16 qsm[];
    __nv_bfloat16* Bh = qsm;
    __nv_bfloat16* Bl = qsm + 128 * QB_STR;
    __shared__ float rsum[128];

    int tid = threadIdx.x, lane = tid & 31, warp = tid >> 5;
    int t0 = blockIdx.x * 128;
    int m0 = (warp >> 1) * 32;
    int t0w = (warp & 1) * 64;

    // stage q tile -> bf16 hi/lo smem
    for (int i = tid * 4; i < 128 * 256; i += 1024) {
        int t = i >> 8, k = i & 255;
        float4 v = *(const float4*)&q[(size_t)(t0 + t) * C_DIM + k];
        float vv[4] = {v.x, v.y, v.z, v.w};
#pragma unroll
        for (int u = 0; u < 4; u++) {
            __nv_bfloat16 h = __float2bfloat16(vv[u]);
            Bh[t * QB_STR + k + u] = h;
            Bl[t * QB_STR + k + u] = __float2bfloat16(vv[u] - __bfloat162float(h));
        }
    }
    // init duty (block 0): zero l1 + addmem for this replay (consumed by k2/k4 later)
    if (blockIdx.x == 0) {
        if (tid < M_DIM) g_l1[tid] = 0.f;
        for (int i = tid * 4; i < M_DIM * C_DIM; i += 1024)
            *(float4*)&g_addmem[i] = make_float4(0.f, 0.f, 0.f, 0.f);
    }
    if (tid < 128) rsum[tid] = 0.f;
    __syncthreads();

    uint32_t sBh = smem_u32(Bh), sBl = smem_u32(Bl);

    float acc[2][8][4];
#pragma unroll
    for (int mf = 0; mf < 2; mf++)
#pragma unroll
        for (int nf = 0; nf < 8; nf++)
#pragma unroll
            for (int u = 0; u < 4; u++) acc[mf][nf][u] = 0.f;

    int g = lane >> 2, t2 = (lane & 3) * 2;
    int lrow = (lane & 7) + ((lane >> 4) << 3);
    int lcol = (lane & 8);

    // prefetch a-frag sources (f32 mem, rows m0..m0+31 per warp pair)
    float2 pf[8];
#pragma unroll
    for (int mf = 0; mf < 2; mf++) {
        int mb = m0 + mf * 16;
        pf[mf * 4 + 0] = *(const float2*)&mem[(mb + g) * C_DIM + t2];
        pf[mf * 4 + 1] = *(const float2*)&mem[(mb + g + 8) * C_DIM + t2];
        pf[mf * 4 + 2] = *(const float2*)&mem[(mb + g) * C_DIM + t2 + 8];
        pf[mf * 4 + 3] = *(const float2*)&mem[(mb + g + 8) * C_DIM + t2 + 8];
    }

    for (int ks = 0; ks < 16; ks++) {
        int k0 = ks * 16;
        float2 f[8];
#pragma unroll
        for (int u = 0; u < 8; u++) f[u] = pf[u];
        if (ks < 15) {
            int kn = k0 + 16;
#pragma unroll
            for (int mf = 0; mf < 2; mf++) {
                int mb = m0 + mf * 16;
                pf[mf * 4 + 0] = *(const float2*)&mem[(mb + g) * C_DIM + kn + t2];
                pf[mf * 4 + 1] = *(const float2*)&mem[(mb + g + 8) * C_DIM + kn + t2];
                pf[mf * 4 + 2] = *(const float2*)&mem[(mb + g) * C_DIM + kn + t2 + 8];
                pf[mf * 4 + 3] = *(const float2*)&mem[(mb + g + 8) * C_DIM + kn + t2 + 8];
            }
        }
        uint32_t ah[2][4], al[2][4];
#pragma unroll
        for (int mf = 0; mf < 2; mf++)
#pragma unroll
            for (int u = 0; u < 4; u++)
                split2(f[mf * 4 + u].x, f[mf * 4 + u].y, ah[mf][u], al[mf][u]);

        uint32_t bh[8][2], bl[8][2];
#pragma unroll
        for (int pr = 0; pr < 4; pr++) {
            int tb = t0w + pr * 16;
            uint32_t off = (uint32_t)((tb + lrow) * QB_STR + k0 + lcol) * 2;
            LDMATRIX_X4(bh[pr * 2][0], bh[pr * 2][1], bh[pr * 2 + 1][0], bh[pr * 2 + 1][1], sBh + off);
            LDMATRIX_X4(bl[pr * 2][0], bl[pr * 2][1], bl[pr * 2 + 1][0], bl[pr * 2 + 1][1], sBl + off);
        }
#pragma unroll
        for (int mf = 0; mf < 2; mf++)
#pragma unroll
            for (int nf = 0; nf < 8; nf++) MMA_BF16(acc[mf][nf], ah[mf], bh[nf]);
#pragma unroll
        for (int mf = 0; mf < 2; mf++)
#pragma unroll
            for (int nf = 0; nf < 8; nf++) MMA_BF16(acc[mf][nf], ah[mf], bl[nf]);
#pragma unroll
        for (int mf = 0; mf < 2; mf++)
#pragma unroll
            for (int nf = 0; nf < 8; nf++) MMA_BF16(acc[mf][nf], al[mf], bh[nf]);
    }

#pragma unroll
    for (int mf = 0; mf < 2; mf++) {
        float p0 = 0.f, p1 = 0.f;
        int mr0 = m0 + mf * 16 + g;
        int mr1 = mr0 + 8;
#pragma unroll
        for (int nf = 0; nf < 8; nf++) {
            int ta = t0 + t0w + nf * 8 + t2;
            float e0 = __expf(acc[mf][nf][0]);
            float e1 = __expf(acc[mf][nf][1]);
            float e2 = __expf(acc[mf][nf][2]);
            float e3 = __expf(acc[mf][nf][3]);
            *(float2*)&g_S[(size_t)mr0 * T_TOT + ta] = make_float2(e0, e1);
            *(float2*)&g_S[(size_t)mr1 * T_TOT + ta] = make_float2(e2, e3);
            p0 += e0 + e1;
            p1 += e2 + e3;
        }
#pragma unroll
        for (int o = 1; o < 4; o <<= 1) {
            p0 += __shfl_xor_sync(0xffffffffu, p0, o);
            p1 += __shfl_xor_sync(0xffffffffu, p1, o);
        }
        if ((lane & 3) == 0) {
            atomicAdd(&rsum[mr0], p0);
            atomicAdd(&rsum[mr1], p1);
        }
    }
    __syncthreads();
    if (tid < 128) g_rowpart[blockIdx.x * 128 + tid] = rsum[tid];
}

// ---------------- K2: rowsum reduce + scan + shrink + l1 + inline sparse scatter ----------------
__global__ __launch_bounds__(256) void k2_scan(const float* __restrict__ q) {
    __shared__ float red[256];
    __shared__ float rs_sh;
    int tid = threadIdx.x, lane = tid & 31;
    int m = blockIdx.y;

    // reduce 512 partials for this m
    float p = g_rowpart[tid * 128 + m] + g_rowpart[(tid + 256) * 128 + m];
    red[tid] = p;
    __syncthreads();
    for (int s = 128; s > 0; s >>= 1) {
        if (tid < s) red[tid] += red[tid + s];
        __syncthreads();
    }
    if (tid == 0) rs_sh = red[0];
    __syncthreads();
    float rs = rs_sh;
    float thr = SHRINKV * rs;
    float inv = 1.0f / rs;

    size_t rowbase = (size_t)m * T_TOT;
    int tbase = blockIdx.x * 16384 + tid * 4;
#pragma unroll
    for (int j = 0; j < 16; j++) {
        int t = tbase + j * 1024;
        float4 v = *(const float4*)&g_S[rowbase + t];
        float e[4] = {v.x, v.y, v.z, v.w};
#pragma unroll
        for (int k = 0; k < 4; k++) {
            bool hit = e[k] > thr;
            float h = 0.f;
            if (hit) {
                float a = e[k] * inv;
                float d = a - SHRINKV;
                h = (d > 0.f) ? d * a / (d + EPSV) : 0.f;
                atomicAdd(&g_l1[m], h);
            }
            unsigned mask = __ballot_sync(0xffffffffu, hit);
            while (mask) {
                int src = __ffs(mask) - 1;
                mask &= mask - 1;
                float hs = __shfl_sync(0xffffffffu, h, src);
                int ts = __shfl_sync(0xffffffffu, t + k, src);
#pragma unroll
                for (int u = 0; u < 8; u++) {
                    int c = lane + u * 32;
                    atomicAdd(&g_addmem[m * C_DIM + c], hs * q[(size_t)ts * C_DIM + c]);
                }
            }
        }
    }
}

// ---------------- K4: gate + new_mem ----------------
__global__ __launch_bounds__(256) void k4_gate(const float* __restrict__ mem,
                                               const float* __restrict__ Uw,
                                               const float* __restrict__ Ub,
                                               const float* __restrict__ Ww,
                                               const float* __restrict__ Wb,
                                               float* __restrict__ nm_out) {
    __shared__ float mr[8][256], ar[8][256];
    int c = threadIdx.x;
    int m0 = blockIdx.x * 8;

    for (int i = 0; i < 8; i++) {
        int m = m0 + i;
        float invl1 = 1.0f / fmaxf(g_l1[m], EPSV);
        mr[i][c] = mem[m * C_DIM + c];
        ar[i][c] = g_addmem[m * C_DIM + c] * invl1;
    }
    __syncthreads();

    float s[8];
    float b = Ub[c] + Wb[c];
#pragma unroll
    for (int i = 0; i < 8; i++) s[i] = b;

    const float* uw = Uw + c * C_DIM;
    const float* ww = Ww + c * C_DIM;
    for (int k = 0; k < C_DIM; k += 4) {
        float4 wu4 = *(const float4*)&uw[k];
        float4 wv4 = *(const float4*)&ww[k];
        float wu[4] = {wu4.x, wu4.y, wu4.z, wu4.w};
        float wv[4] = {wv4.x, wv4.y, wv4.z, wv4.w};
#pragma unroll
        for (int u = 0; u < 4; u++)
#pragma unroll
            for (int i = 0; i < 8; i++)
                s[i] += mr[i][k + u] * wu[u] + ar[i][k + u] * wv[u];
    }
#pragma unroll
    for (int i = 0; i < 8; i++) {
        int m = m0 + i;
        float g = 1.f / (1.f + __expf(-s[i]));
        float nm = (1.f - g) * mr[i][c] + g * ar[i][c];
        g_newmem[m * C_DIM + c] = nm;
        nm_out[m * C_DIM + c] = nm;
    }
}

// ---------------- K5: fused read phase via mma.sync, pass-major + prefetch ----------------
#define NMS 264
__global__ __launch_bounds__(256) void k5_mma(const float* __restrict__ q,
                                              float* __restrict__ out,
                                              float* __restrict__ attn) {
    extern __shared__ __nv_bfloat16 sm5[];
    __nv_bfloat16* Nh = sm5;
    __nv_bfloat16* Nl = sm5 + 128 * NMS;

    int tid = threadIdx.x, lane = tid & 31, warp = tid >> 5;
    size_t T0 = (size_t)blockIdx.x * 128;

    for (int i = tid * 2; i < 128 * 256; i += 512) {
        int m = i >> 8, c = i & 255;
        float2 v = *(const float2*)&g_newmem[i];
        uint32_t hi, lo;
        split2(v.x, v.y, hi, lo);
        *(uint32_t*)&Nh[m * NMS + c] = hi;
        *(uint32_t*)&Nl[m * NMS + c] = lo;
    }
    for (int l = tid * 4; l < 128 * 256; l += 1024) {
        int t = l >> 8, c = l & 255;
        float4 v = *(const float4*)&q[T0 * C_DIM + l];
        *(float4*)&out[(T0 + t) * 512 + c] = v;
    }
    __syncthreads();

    uint32_t sNh = smem_u32(Nh), sNl = smem_u32(Nl);

    int g = lane >> 2, t2 = (lane & 3) * 2;
    int lrow = (lane & 7) + ((lane >> 4) << 3);
    int lcol = (lane & 8);
    int tw = warp * 16;
    size_t rowg = T0 + tw + g;
    size_t rowg8 = rowg + 8;

    // ==== phase 1: scores 16t x 128m ====
    float acc[16][4];
#pragma unroll
    for (int j = 0; j < 16; j++)
#pragma unroll
        for (int u = 0; u < 4; u++) acc[j][u] = 0.f;

    float2 pf0 = *(const float2*)&q[rowg * C_DIM + t2];
    float2 pf1 = *(const float2*)&q[rowg8 * C_DIM + t2];
    float2 pf2 = *(const float2*)&q[rowg * C_DIM + t2 + 8];
    float2 pf3 = *(const float2*)&q[rowg8 * C_DIM + t2 + 8];

    for (int ks = 0; ks < 16; ks++) {
        int k0 = ks * 16;
        float2 f0 = pf0, f1 = pf1, f2 = pf2, f3 = pf3;
        if (ks < 15) {
            int kn = k0 + 16;
            pf0 = *(const float2*)&q[rowg * C_DIM + kn + t2];
            pf1 = *(const float2*)&q[rowg8 * C_DIM + kn + t2];
            pf2 = *(const float2*)&q[rowg * C_DIM + kn + t2 + 8];
            pf3 = *(const float2*)&q[rowg8 * C_DIM + kn + t2 + 8];
        }
        uint32_t ah[4], al[4];
        split2(f0.x, f0.y, ah[0], al[0]);
        split2(f1.x, f1.y, ah[1], al[1]);
        split2(f2.x, f2.y, ah[2], al[2]);
        split2(f3.x, f3.y, ah[3], al[3]);

        uint32_t bh[16][2], bl[16][2];
#pragma unroll
        for (int bp = 0; bp < 8; bp++) {
            uint32_t off = (uint32_t)((16 * bp + lrow) * NMS + k0 + lcol) * 2;
            LDMATRIX_X4(bh[2 * bp][0], bh[2 * bp][1], bh[2 * bp + 1][0], bh[2 * bp + 1][1], sNh + off);
            LDMATRIX_X4(bl[2 * bp][0], bl[2 * bp][1], bl[2 * bp + 1][0], bl[2 * bp + 1][1], sNl + off);
        }
#pragma unroll
        for (int j = 0; j < 16; j++) MMA_BF16(acc[j], ah, bh[j]);
#pragma unroll
        for (int j = 0; j < 16; j++) MMA_BF16(acc[j], ah, bl[j]);
#pragma unroll
        for (int j = 0; j < 16; j++) MMA_BF16(acc[j], al, bh[j]);
    }

    // ==== softmax + shrink + l1-normalize (quad-local) ====
    {
        float mx0 = -1e30f, mx1 = -1e30f;
#pragma unroll
        for (int j = 0; j < 16; j++) {
            mx0 = fmaxf(mx0, fmaxf(acc[j][0], acc[j][1]));
            mx1 = fmaxf(mx1, fmaxf(acc[j][2], acc[j][3]));
        }
#pragma unroll
        for (int o = 1; o < 4; o <<= 1) {
            mx0 = fmaxf(mx0, __shfl_xor_sync(0xffffffffu, mx0, o));
            mx1 = fmaxf(mx1, __shfl_xor_sync(0xffffffffu, mx1, o));
        }
        float s0 = 0.f, s1 = 0.f;
#pragma unroll
        for (int j = 0; j < 16; j++) {
            acc[j][0] = __expf(acc[j][0] - mx0);
            acc[j][1] = __expf(acc[j][1] - mx0);
            acc[j][2] = __expf(acc[j][2] - mx1);
            acc[j][3] = __expf(acc[j][3] - mx1);
            s0 += acc[j][0] + acc[j][1];
            s1 += acc[j][2] + acc[j][3];
        }
#pragma unroll
        for (int o = 1; o < 4; o <<= 1) {
            s0 += __shfl_xor_sync(0xffffffffu, s0, o);
            s1 += __shfl_xor_sync(0xffffffffu, s1, o);
        }
        float i0 = 1.f / s0, i1 = 1.f / s1;
        float l10 = 0.f, l11 = 0.f;
#pragma unroll
        for (int j = 0; j < 16; j++) {
            float a0 = acc[j][0] * i0, a1 = acc[j][1] * i0;
            float a2 = acc[j][2] * i1, a3 = acc[j][3] * i1;
            float d0 = a0 - SHRINKV, d1 = a1 - SHRINKV;
            float d2 = a2 - SHRINKV, d3 = a3 - SHRINKV;
            acc[j][0] = (d0 > 0.f) ? __fdividef(d0 * a0, d0 + EPSV) : 0.f;
            acc[j][1] = (d1 > 0.f) ? __fdividef(d1 * a1, d1 + EPSV) : 0.f;
            acc[j][2] = (d2 > 0.f) ? __fdividef(d2 * a2, d2 + EPSV) : 0.f;
            acc[j][3] = (d3 > 0.f) ? __fdividef(d3 * a3, d3 + EPSV) : 0.f;
            l10 += acc[j][0] + acc[j][1];
            l11 += acc[j][2] + acc[j][3];
        }
#pragma unroll
        for (int o = 1; o < 4; o <<= 1) {
            l10 += __shfl_xor_sync(0xffffffffu, l10, o);
            l11 += __shfl_xor_sync(0xffffffffu, l11, o);
        }
        float n0 = 1.f / fmaxf(l10, EPSV), n1 = 1.f / fmaxf(l11, EPSV);
#pragma unroll
        for (int j = 0; j < 16; j++) {
            acc[j][0] *= n0; acc[j][1] *= n0;
            acc[j][2] *= n1; acc[j][3] *= n1;
            int mm = 8 * j + t2;
            *(float2*)&attn[rowg * M_DIM + mm] = make_float2(acc[j][0], acc[j][1]);
            *(float2*)&attn[rowg8 * M_DIM + mm] = make_float2(acc[j][2], acc[j][3]);
        }
    }

    // ==== h -> a-frags bf16 hi/lo ====
    uint32_t hh[8][4], hl[8][4];
#pragma unroll
    for (int s = 0; s < 8; s++) {
        split2(acc[2 * s][0], acc[2 * s][1], hh[s][0], hl[s][0]);
        split2(acc[2 * s][2], acc[2 * s][3], hh[s][1], hl[s][1]);
        split2(acc[2 * s + 1][0], acc[2 * s + 1][1], hh[s][2], hl[s][2]);
        split2(acc[2 * s + 1][2], acc[2 * s + 1][3], hh[s][3], hl[s][3]);
    }

    // ==== phase 2: add_memory 16t x 256c (two 128c passes) ====
#pragma unroll
    for (int p = 0; p < 2; p++) {
        float ac2[16][4];
#pragma unroll
        for (int j = 0; j < 16; j++)
#pragma unroll
            for (int u = 0; u < 4; u++) ac2[j][u] = 0.f;

#pragma unroll
        for (int s = 0; s < 8; s++) {
            uint32_t bh[16][2], bl[16][2];
#pragma unroll
            for (int np = 0; np < 8; np++) {
                uint32_t off = (uint32_t)((16 * s + (lane & 15)) * NMS
                              + p * 128 + np * 16 + ((lane >> 4) * 8)) * 2;
                LDMATRIX_X4T(bh[2 * np][0], bh[2 * np][1], bh[2 * np + 1][0], bh[2 * np + 1][1], sNh + off);
                LDMATRIX_X4T(bl[2 * np][0], bl[2 * np][1], bl[2 * np + 1][0], bl[2 * np + 1][1], sNl + off);
            }
#pragma unroll
            for (int j = 0; j < 16; j++) MMA_BF16(ac2[j], hh[s], bh[j]);
#pragma unroll
            for (int j = 0; j < 16; j++) MMA_BF16(ac2[j], hh[s], bl[j]);
#pragma unroll
            for (int j = 0; j < 16; j++) MMA_BF16(ac2[j], hl[s], bh[j]);
        }
#pragma unroll
        for (int nf = 0; nf < 16; nf++) {
            int c = 256 + p * 128 + nf * 8 + t2;
            *(float2*)&out[rowg * 512 + c] = make_float2(ac2[nf][0], ac2[nf][1]);
            *(float2*)&out[rowg8 * 512 + c] = make_float2(ac2[nf][2], ac2[nf][3]);
        }
    }
}

// ---------------- launcher ----------------
extern "C" void kernel_launch(void* const* d_in, const int* in_sizes, int n_in,
                              void* d_out, int out_size) {
    const float* query = (const float*)d_in[0];
    const float* mem   = (const float*)d_in[1];
    const float* Uw    = (const float*)d_in[2];
    const float* Ub    = (const float*)d_in[3];
    const float* Ww    = (const float*)d_in[4];
    const float* Wb    = (const float*)d_in[5];

    float* out  = (float*)d_out;
    float* attn = out + (size_t)T_TOT * 512;
    float* nmo  = attn + (size_t)T_TOT * M_DIM;

    const int SMEM1 = 2 * 128 * QB_STR * 2;
    const int SMEM5 = 2 * 128 * NMS * 2;
    cudaFuncSetAttribute(k1_mma, cudaFuncAttributeMaxDynamicSharedMemorySize, SMEM1);
    cudaFuncSetAttribute(k5_mma, cudaFuncAttributeMaxDynamicSharedMemorySize, SMEM5);

    k1_mma<<<T_TOT / 128, 256, SMEM1>>>(query, mem);
    k2_scan<<<dim3(4, 128), 256>>>(query);
    k4_gate<<<16, 256>>>(mem, Uw, Ub, Ww, Wb, nmo);
    k5_mma<<<T_TOT / 128, 256, SMEM5>>>(query, out, attn);
}